// round 12
// baseline (speedup 1.0000x reference)
#include <cuda_runtime.h>
#include <cuda_bf16.h>
#include <math.h>
#include <stdint.h>

// ---------------------------------------------------------------------------
// Problem constants
// ---------------------------------------------------------------------------
#define Nn 16            // B*T
#define Cc 512
#define Ss 1024          // H*W
#define NHEADS 8
#define HD 64
#define D3 1536          // 3*C

typedef __nv_bfloat16 bf16;

// ---------------------------------------------------------------------------
// Scratch (device globals; no cudaMalloc allowed)
// ---------------------------------------------------------------------------
__device__ bf16 g_hn   [Nn * Ss * Cc];           // [n][s][c]
__device__ bf16 g_q    [Nn * NHEADS * Ss * HD];  // [nh][s][e]
__device__ bf16 g_k    [Nn * NHEADS * Ss * HD];  // [nh][s][e]
__device__ bf16 g_v    [Nn * NHEADS * HD * Ss];  // [nh][e][s] (transposed)
__device__ bf16 g_att  [Nn * Ss * Cc];           // [n][s][c]
__device__ bf16 g_wqkvT[D3 * Cc];                // [d][c]
__device__ bf16 g_woutT[Cc * Cc];                // [c2][c]

// ---------------------------------------------------------------------------
// Helpers
// ---------------------------------------------------------------------------
__device__ __forceinline__ uint32_t smem_u32(const void* p) {
    uint32_t a;
    asm("{ .reg .u64 t; cvta.to.shared.u64 t, %1; cvt.u32.u64 %0, t; }"
        : "=r"(a) : "l"(p));
    return a;
}

// pack two fp32 -> bf16x2 (lo = first arg)
__device__ __forceinline__ uint32_t packbf(float lo, float hi) {
    uint32_t r;
    asm("cvt.rn.bf16x2.f32 %0, %1, %2;" : "=r"(r) : "f"(hi), "f"(lo));
    return r;
}

// m16n8k16 bf16 mma, D = A*B + D (in place), fp32 accumulate
__device__ __forceinline__ void mma16(float* d, const uint32_t* a, const uint32_t* b) {
    asm volatile(
        "mma.sync.aligned.m16n8k16.row.col.f32.bf16.bf16.f32 "
        "{%0,%1,%2,%3}, {%4,%5,%6,%7}, {%8,%9}, {%0,%1,%2,%3};"
        : "+f"(d[0]), "+f"(d[1]), "+f"(d[2]), "+f"(d[3])
        : "r"(a[0]), "r"(a[1]), "r"(a[2]), "r"(a[3]), "r"(b[0]), "r"(b[1]));
}

__device__ __forceinline__ void cp16(uint32_t dst, const void* src) {
    asm volatile("cp.async.cg.shared.global [%0], [%1], 16;" :: "r"(dst), "l"(src));
}
#define CP_COMMIT() asm volatile("cp.async.commit_group;" ::: "memory")
#define CP_WAIT1()  asm volatile("cp.async.wait_group 1;" ::: "memory")

// ---------------------------------------------------------------------------
// Kernel 0: weight transpose + bf16 rounding   in [512][Ccols] -> out [Ccols][512]
// ---------------------------------------------------------------------------
__global__ void __launch_bounds__(256) trans_kernel(const float* __restrict__ in,
                                                    int Ccols, int which)
{
    bf16* out = which ? g_woutT : g_wqkvT;
    __shared__ float t[32][33];
    int c0 = blockIdx.x * 32, r0 = blockIdx.y * 32;
    int tx = threadIdx.x, ty = threadIdx.y;
#pragma unroll
    for (int i = 0; i < 32; i += 8)
        t[ty + i][tx] = in[(size_t)(r0 + ty + i) * Ccols + c0 + tx];
    __syncthreads();
#pragma unroll
    for (int i = 0; i < 32; i += 8)
        out[(size_t)(c0 + ty + i) * 512 + r0 + tx] = __float2bfloat16_rn(t[tx][ty + i]);
}

// ---------------------------------------------------------------------------
// Kernel 1: GroupNorm (32 groups, eps=1e-6) -> g_hn [n][s][c] (bf16)
// ---------------------------------------------------------------------------
__global__ void __launch_bounds__(256) gn_kernel(const float* __restrict__ x,
                                                 const float* __restrict__ sc,
                                                 const float* __restrict__ bi)
{
    extern __shared__ float smt[];   // [1024][17]
    int n = blockIdx.x >> 5;
    int g = blockIdx.x & 31;
    const float* px = x + (size_t)(n * Cc + g * 16) * Ss;
    bf16* ph = g_hn + (size_t)n * Ss * Cc + g * 16;
    int tid = threadIdx.x;
    const int M = 16 * Ss;

    float s = 0.f, ss = 0.f;
    for (int i = tid * 4; i < M; i += 1024) {
        float4 v = *(const float4*)&px[i];
        s  += v.x + v.y + v.z + v.w;
        ss += v.x*v.x + v.y*v.y + v.z*v.z + v.w*v.w;
    }
#pragma unroll
    for (int o = 16; o; o >>= 1) {
        s  += __shfl_xor_sync(0xffffffffu, s,  o);
        ss += __shfl_xor_sync(0xffffffffu, ss, o);
    }
    __shared__ float r0[8], r1[8];
    __shared__ float s_mean, s_inv;
    if ((tid & 31) == 0) { r0[tid >> 5] = s; r1[tid >> 5] = ss; }
    __syncthreads();
    if (tid == 0) {
        float a = 0.f, b2 = 0.f;
#pragma unroll
        for (int i = 0; i < 8; i++) { a += r0[i]; b2 += r1[i]; }
        float mean = a / (float)M;
        float var  = b2 / (float)M - mean * mean;
        s_mean = mean;
        s_inv  = rsqrtf(var + 1e-6f);
    }
    __syncthreads();
    float mean = s_mean, inv = s_inv;

    for (int i = tid * 4; i < M; i += 1024) {
        int c  = i >> 10;
        int sp = i & 1023;
        float scv = sc[g * 16 + c] * inv;
        float biv = bi[g * 16 + c] - mean * scv;
        float4 v = *(const float4*)&px[i];
        smt[(sp + 0) * 17 + c] = v.x * scv + biv;
        smt[(sp + 1) * 17 + c] = v.y * scv + biv;
        smt[(sp + 2) * 17 + c] = v.z * scv + biv;
        smt[(sp + 3) * 17 + c] = v.w * scv + biv;
    }
    __syncthreads();

    // write 16-bf16 rows (32 B = 2 x 16B stores)
#pragma unroll
    for (int j = 0; j < 4; j++) {
        int sp = tid * 4 + j;
        const float* row = &smt[sp * 17];
        uint32_t pk[8];
#pragma unroll
        for (int q = 0; q < 8; q++) pk[q] = packbf(row[2*q], row[2*q+1]);
        uint4* dst = (uint4*)(ph + (size_t)sp * Cc);
        dst[0] = make_uint4(pk[0], pk[1], pk[2], pk[3]);
        dst[1] = make_uint4(pk[4], pk[5], pk[6], pk[7]);
    }
}

// ---------------------------------------------------------------------------
// Kernel 2: bf16 m16n8k16 GEMM, tile 128x128, K=512, BK=32, 3-stage cp.async.
// 512 threads = 16 warps as 4(M) x 4(N); warp tile 32x32 -> 32 accum regs,
// <=64 regs so 2 CTAs/SM = 32 warps/SM (occ ~48%) — bf16 halves tensor work,
// so occupancy (not traffic) is the binder; thin warps + high occ wins.
// SMEM: bf16, row stride 40 (80 B); stage = 20480 B, 3 stages = 61440 B.
// ---------------------------------------------------------------------------
__device__ __forceinline__ void gemm_load(uint32_t sbase, int soff,
                                          const bf16* __restrict__ Ag,
                                          const bf16* __restrict__ Bg,
                                          int koff, int tid)
{
    // 512 threads cover rows 0..127, chunks 0..3 exactly once (A and B each)
    int row = tid >> 2, c = tid & 3;
    cp16(sbase + (uint32_t)(soff + row * 80 + c * 16),
         Ag + (size_t)row * Cc + koff + c * 8);
    cp16(sbase + (uint32_t)(soff + 10240 + row * 80 + c * 16),
         Bg + (size_t)row * Cc + koff + c * 8);
}

__global__ void __launch_bounds__(512, 2) gemm_mma(const float* __restrict__ bias,
                                                   const float* __restrict__ xres,
                                                   float* __restrict__ out,
                                                   int mode)
{
    extern __shared__ char smc[];
    uint32_t sbase = smem_u32(smc);
    int tid = threadIdx.x, lane = tid & 31, wid = tid >> 5;
    int g = lane >> 2, tg = lane & 3;
    int n = blockIdx.z, s0 = blockIdx.x * 128, d0 = blockIdx.y * 128;
    int wm = wid & 3, wn = wid >> 2;

    const bf16* Ag = (mode ? g_att : g_hn) + ((size_t)n * Ss + s0) * Cc;
    const bf16* Bg = (mode ? g_woutT : g_wqkvT) + (size_t)d0 * Cc;

    float C[2][4][4] = {};

    gemm_load(sbase, 0, Ag, Bg, 0, tid);
    CP_COMMIT();
    gemm_load(sbase, 20480, Ag, Bg, 32, tid);
    CP_COMMIT();

    for (int kc = 0; kc < 16; kc++) {
        CP_WAIT1();
        __syncthreads();
        int b = kc % 3;
        if (kc + 2 < 16)
            gemm_load(sbase, ((kc + 2) % 3) * 20480, Ag, Bg, (kc + 2) * 32, tid);
        CP_COMMIT();

        const bf16* As = (const bf16*)(smc + b * 20480);
        const bf16* Bs = (const bf16*)(smc + b * 20480 + 10240);
#pragma unroll
        for (int ks = 0; ks < 2; ks++) {       // two k16 steps per BK=32
            int k0 = ks * 16;
            uint32_t a[2][4], bb[4][2];
#pragma unroll
            for (int tm = 0; tm < 2; tm++) {
                int r = wm * 32 + tm * 16 + g;
                a[tm][0] = *(const uint32_t*)&As[r * 40 + k0 + 2 * tg];
                a[tm][1] = *(const uint32_t*)&As[(r + 8) * 40 + k0 + 2 * tg];
                a[tm][2] = *(const uint32_t*)&As[r * 40 + k0 + 2 * tg + 8];
                a[tm][3] = *(const uint32_t*)&As[(r + 8) * 40 + k0 + 2 * tg + 8];
            }
#pragma unroll
            for (int tn = 0; tn < 4; tn++) {
                int c = wn * 32 + tn * 8 + g;
                bb[tn][0] = *(const uint32_t*)&Bs[c * 40 + k0 + 2 * tg];
                bb[tn][1] = *(const uint32_t*)&Bs[c * 40 + k0 + 2 * tg + 8];
            }
#pragma unroll
            for (int tm = 0; tm < 2; tm++)
#pragma unroll
                for (int tn = 0; tn < 4; tn++)
                    mma16(C[tm][tn], a[tm], bb[tn]);
        }
    }

    // epilogue
#pragma unroll
    for (int tm = 0; tm < 2; tm++) {
#pragma unroll
        for (int hh = 0; hh < 2; hh++) {
            int m = s0 + wm * 32 + tm * 16 + g + hh * 8;
#pragma unroll
            for (int tn = 0; tn < 4; tn++) {
                int d = d0 + wn * 32 + tn * 8 + 2 * tg;
                float v0 = C[tm][tn][hh * 2 + 0] + __ldg(&bias[d]);
                float v1 = C[tm][tn][hh * 2 + 1] + __ldg(&bias[d + 1]);
                if (mode == 0) {
                    int head = d / 192, t = d % 192;
                    int part = t >> 6, e = t & 63;
                    size_t nh = (size_t)(n * 8 + head);
                    if (part == 0) {
                        *(uint32_t*)&g_q[(nh * Ss + m) * HD + e] = packbf(v0, v1);
                    } else if (part == 1) {
                        *(uint32_t*)&g_k[(nh * Ss + m) * HD + e] = packbf(v0, v1);
                    } else {
                        g_v[(nh * HD + e) * Ss + m]     = __float2bfloat16_rn(v0);
                        g_v[(nh * HD + e + 1) * Ss + m] = __float2bfloat16_rn(v1);
                    }
                } else {
                    size_t gi = ((size_t)n * Cc + d) * Ss + m;
                    out[gi]      = v0 + xres[gi];
                    out[gi + Ss] = v1 + xres[gi + Ss];
                }
            }
        }
    }
}

// ---------------------------------------------------------------------------
// Kernel 3: flash attention, bf16 m16n8k16, double-buffered cp.async K/V.
// 512 threads = 16 warps of 16 q rows -> q-tile 256: K/V traffic amortized
// over 2x q rows vs the 128-row tile. P stays in registers (bf16 C-frag
// layout == A-frag layout, no shuffles).
// SMEM bytes: KV stage b: K at b*18432, V at +9216; Q at 36864 (256x144).
// Total 73728. 1 CTA/SM (regs ~126).
// ---------------------------------------------------------------------------
#define ATT_SMEM 73728

__device__ __forceinline__ void attn_load_kv(uint32_t sbase, int b,
                                             const bf16* __restrict__ K,
                                             const bf16* __restrict__ V,
                                             int kt, int tid)
{
    // 512 threads cover 64 rows x 8 chunks for K and V each
    int r = tid >> 3, c = tid & 7;
    cp16(sbase + (uint32_t)(b * 18432 + r * 144 + c * 16),
         K + (size_t)(kt * 64 + r) * HD + c * 8);
    cp16(sbase + (uint32_t)(b * 18432 + 9216 + r * 144 + c * 16),
         V + (size_t)r * Ss + kt * 64 + c * 8);
}

__global__ void __launch_bounds__(512, 1) attn_mma()
{
    extern __shared__ char smc[];
    uint32_t sbase = smem_u32(smc);
    const bf16* Qs = (const bf16*)(smc + 36864);

    int tid = threadIdx.x, lane = tid & 31, w = tid >> 5;
    int g = lane >> 2, tg = lane & 3;
    int nh = blockIdx.y, q0 = blockIdx.x * 256;
    const bf16* Q = g_q + (size_t)nh * Ss * HD;
    const bf16* K = g_k + (size_t)nh * Ss * HD;
    const bf16* V = g_v + (size_t)nh * HD * Ss;

    // prologue: Q (256 rows) + KV(0) -> group 0; KV(1) -> group 1
#pragma unroll
    for (int i = 0; i < 4; i++) {
        int f = tid + i * 512;
        int row = f >> 3, c = f & 7;
        cp16(sbase + (uint32_t)(36864 + row * 144 + c * 16),
             Q + (size_t)(q0 + row) * HD + c * 8);
    }
    attn_load_kv(sbase, 0, K, V, 0, tid);
    CP_COMMIT();
    attn_load_kv(sbase, 1, K, V, 1, tid);
    CP_COMMIT();

    float O[8][4] = {};
    float m0 = -1e30f, m1 = -1e30f, l0 = 0.f, l1 = 0.f;
    int qb = w * 16;

    for (int kt = 0; kt < 16; kt++) {
        CP_WAIT1();
        __syncthreads();
        int b = kt & 1;
        const bf16* Ks = (const bf16*)(smc + b * 18432);
        const bf16* Vs = (const bf16*)(smc + b * 18432 + 9216);

        // S = Q @ K^T  (warp: 16 q rows x 64 keys), k-dim = e: 4 k16 steps
        float S[8][4] = {};
#pragma unroll
        for (int ks = 0; ks < 4; ks++) {
            int k0 = ks * 16;
            uint32_t a[4];
            a[0] = *(const uint32_t*)&Qs[(qb + g) * 72 + k0 + 2 * tg];
            a[1] = *(const uint32_t*)&Qs[(qb + g + 8) * 72 + k0 + 2 * tg];
            a[2] = *(const uint32_t*)&Qs[(qb + g) * 72 + k0 + 2 * tg + 8];
            a[3] = *(const uint32_t*)&Qs[(qb + g + 8) * 72 + k0 + 2 * tg + 8];
#pragma unroll
            for (int tn = 0; tn < 8; tn++) {
                uint32_t bfr[2];
                bfr[0] = *(const uint32_t*)&Ks[(tn * 8 + g) * 72 + k0 + 2 * tg];
                bfr[1] = *(const uint32_t*)&Ks[(tn * 8 + g) * 72 + k0 + 2 * tg + 8];
                mma16(S[tn], a, bfr);
            }
        }

        // scale + online softmax
        float mx0 = -1e30f, mx1 = -1e30f;
#pragma unroll
        for (int tn = 0; tn < 8; tn++) {
            S[tn][0] *= 0.125f; S[tn][1] *= 0.125f;
            S[tn][2] *= 0.125f; S[tn][3] *= 0.125f;
            mx0 = fmaxf(mx0, fmaxf(S[tn][0], S[tn][1]));
            mx1 = fmaxf(mx1, fmaxf(S[tn][2], S[tn][3]));
        }
        mx0 = fmaxf(mx0, __shfl_xor_sync(0xffffffffu, mx0, 1));
        mx0 = fmaxf(mx0, __shfl_xor_sync(0xffffffffu, mx0, 2));
        mx1 = fmaxf(mx1, __shfl_xor_sync(0xffffffffu, mx1, 1));
        mx1 = fmaxf(mx1, __shfl_xor_sync(0xffffffffu, mx1, 2));
        float mn0 = fmaxf(m0, mx0), mn1 = fmaxf(m1, mx1);
        float cr0 = __expf(m0 - mn0), cr1 = __expf(m1 - mn1);
        float rs0 = 0.f, rs1 = 0.f;
        uint32_t Pp[8][2];
#pragma unroll
        for (int tn = 0; tn < 8; tn++) {
            S[tn][0] = __expf(S[tn][0] - mn0);
            S[tn][1] = __expf(S[tn][1] - mn0);
            S[tn][2] = __expf(S[tn][2] - mn1);
            S[tn][3] = __expf(S[tn][3] - mn1);
            rs0 += S[tn][0] + S[tn][1];
            rs1 += S[tn][2] + S[tn][3];
            Pp[tn][0] = packbf(S[tn][0], S[tn][1]);
            Pp[tn][1] = packbf(S[tn][2], S[tn][3]);
        }
        rs0 += __shfl_xor_sync(0xffffffffu, rs0, 1);
        rs0 += __shfl_xor_sync(0xffffffffu, rs0, 2);
        rs1 += __shfl_xor_sync(0xffffffffu, rs1, 1);
        rs1 += __shfl_xor_sync(0xffffffffu, rs1, 2);
        l0 = l0 * cr0 + rs0;  l1 = l1 * cr1 + rs1;
        m0 = mn0;  m1 = mn1;

#pragma unroll
        for (int tn = 0; tn < 8; tn++) {
            O[tn][0] *= cr0; O[tn][1] *= cr0;
            O[tn][2] *= cr1; O[tn][3] *= cr1;
        }

        // O += P @ V : 4 k16 steps over j (P from registers, no shuffles)
#pragma unroll
        for (int ks = 0; ks < 4; ks++) {
            int k0 = ks * 16;
            uint32_t a[4];
            a[0] = Pp[2 * ks][0];
            a[1] = Pp[2 * ks][1];
            a[2] = Pp[2 * ks + 1][0];
            a[3] = Pp[2 * ks + 1][1];
#pragma unroll
            for (int tn = 0; tn < 8; tn++) {
                uint32_t bfr[2];
                bfr[0] = *(const uint32_t*)&Vs[(tn * 8 + g) * 72 + k0 + 2 * tg];
                bfr[1] = *(const uint32_t*)&Vs[(tn * 8 + g) * 72 + k0 + 2 * tg + 8];
                mma16(O[tn], a, bfr);
            }
        }

        __syncthreads();
        if (kt + 2 < 16)
            attn_load_kv(sbase, b, K, V, kt + 2, tid);
        CP_COMMIT();
    }

    // epilogue -> g_att[n][s][head*64 + e] (bf16 pairs)
    int n = nh >> 3, head = nh & 7;
    float inv0 = 1.f / l0, inv1 = 1.f / l1;
    int srow0 = q0 + qb + g, srow1 = srow0 + 8;
    bf16* dst = g_att + (size_t)n * Ss * Cc + head * 64;
#pragma unroll
    for (int tn = 0; tn < 8; tn++) {
        int c = tn * 8 + 2 * tg;
        *(uint32_t*)&dst[(size_t)srow0 * Cc + c] = packbf(O[tn][0] * inv0, O[tn][1] * inv0);
        *(uint32_t*)&dst[(size_t)srow1 * Cc + c] = packbf(O[tn][2] * inv1, O[tn][3] * inv1);
    }
}

// ---------------------------------------------------------------------------
extern "C" void kernel_launch(void* const* d_in, const int* in_sizes, int n_in,
                              void* d_out, int out_size)
{
    const float* x    = (const float*)d_in[0];
    const float* gsc  = (const float*)d_in[1];
    const float* gbi  = (const float*)d_in[2];
    const float* wqkv = (const float*)d_in[3];
    const float* bqkv = (const float*)d_in[4];
    const float* wout = (const float*)d_in[5];
    const float* bout = (const float*)d_in[6];
    float* out = (float*)d_out;

    trans_kernel<<<dim3(D3 / 32, Cc / 32), dim3(32, 8)>>>(wqkv, D3, 0);
    trans_kernel<<<dim3(Cc / 32, Cc / 32), dim3(32, 8)>>>(wout, Cc, 1);

    cudaFuncSetAttribute(gn_kernel, cudaFuncAttributeMaxDynamicSharedMemorySize, 69632);
    gn_kernel<<<Nn * 32, 256, 69632>>>(x, gsc, gbi);

    const int gemm_smem = 61440;   // 3 stages x 20480 B
    cudaFuncSetAttribute(gemm_mma, cudaFuncAttributeMaxDynamicSharedMemorySize, gemm_smem);
    gemm_mma<<<dim3(Ss / 128, D3 / 128, Nn), 512, gemm_smem>>>(bqkv, nullptr, nullptr, 0);

    cudaFuncSetAttribute(attn_mma, cudaFuncAttributeMaxDynamicSharedMemorySize, ATT_SMEM);
    attn_mma<<<dim3(Ss / 256, Nn * NHEADS), 512, ATT_SMEM>>>();

    gemm_mma<<<dim3(Ss / 128, Cc / 128, Nn), 512, gemm_smem>>>(bout, x, out, 1);
}

// round 13
// speedup vs baseline: 1.0805x; 1.0805x over previous
#include <cuda_runtime.h>
#include <cuda_bf16.h>
#include <math.h>
#include <stdint.h>

// ---------------------------------------------------------------------------
// Problem constants
// ---------------------------------------------------------------------------
#define Nn 16            // B*T
#define Cc 512
#define Ss 1024          // H*W
#define NHEADS 8
#define HD 64
#define D3 1536          // 3*C

typedef __nv_bfloat16 bf16;

// ---------------------------------------------------------------------------
// Scratch (device globals; no cudaMalloc allowed)
// ---------------------------------------------------------------------------
__device__ bf16 g_hn   [Nn * Ss * Cc];           // [n][s][c]
__device__ bf16 g_q    [Nn * NHEADS * Ss * HD];  // [nh][s][e]
__device__ bf16 g_k    [Nn * NHEADS * Ss * HD];  // [nh][s][e]
__device__ bf16 g_v    [Nn * NHEADS * HD * Ss];  // [nh][e][s] (transposed)
__device__ bf16 g_att  [Nn * Ss * Cc];           // [n][s][c]
__device__ bf16 g_wqkvT[D3 * Cc];                // [d][c]
__device__ bf16 g_woutT[Cc * Cc];                // [c2][c]

// ---------------------------------------------------------------------------
// Helpers
// ---------------------------------------------------------------------------
__device__ __forceinline__ uint32_t smem_u32(const void* p) {
    uint32_t a;
    asm("{ .reg .u64 t; cvta.to.shared.u64 t, %1; cvt.u32.u64 %0, t; }"
        : "=r"(a) : "l"(p));
    return a;
}

// pack two fp32 -> bf16x2 (lo = first arg)
__device__ __forceinline__ uint32_t packbf(float lo, float hi) {
    uint32_t r;
    asm("cvt.rn.bf16x2.f32 %0, %1, %2;" : "=r"(r) : "f"(hi), "f"(lo));
    return r;
}

// m16n8k16 bf16 mma, D = A*B + D (in place), fp32 accumulate
__device__ __forceinline__ void mma16(float* d, const uint32_t* a, const uint32_t* b) {
    asm volatile(
        "mma.sync.aligned.m16n8k16.row.col.f32.bf16.bf16.f32 "
        "{%0,%1,%2,%3}, {%4,%5,%6,%7}, {%8,%9}, {%0,%1,%2,%3};"
        : "+f"(d[0]), "+f"(d[1]), "+f"(d[2]), "+f"(d[3])
        : "r"(a[0]), "r"(a[1]), "r"(a[2]), "r"(a[3]), "r"(b[0]), "r"(b[1]));
}

__device__ __forceinline__ void cp16(uint32_t dst, const void* src) {
    asm volatile("cp.async.cg.shared.global [%0], [%1], 16;" :: "r"(dst), "l"(src));
}
#define CP_COMMIT() asm volatile("cp.async.commit_group;" ::: "memory")
#define CP_WAIT1()  asm volatile("cp.async.wait_group 1;" ::: "memory")

// ---------------------------------------------------------------------------
// Kernel 0: both weight transposes + bf16 rounding in ONE launch.
// grid (16, 16, 4): z in 0..2 -> w_qkv column blocks; z == 3 -> w_out.
// ---------------------------------------------------------------------------
__global__ void __launch_bounds__(256) trans_kernel(const float* __restrict__ wqkv,
                                                    const float* __restrict__ wout)
{
    int z = blockIdx.z;
    const float* in = (z < 3) ? wqkv : wout;
    bf16* out       = (z < 3) ? g_wqkvT : g_woutT;
    int Ccols       = (z < 3) ? D3 : Cc;
    int c0 = ((z < 3) ? (z * 16 + blockIdx.x) : blockIdx.x) * 32;
    int r0 = blockIdx.y * 32;

    __shared__ float t[32][33];
    int tx = threadIdx.x, ty = threadIdx.y;
#pragma unroll
    for (int i = 0; i < 32; i += 8)
        t[ty + i][tx] = in[(size_t)(r0 + ty + i) * Ccols + c0 + tx];
    __syncthreads();
#pragma unroll
    for (int i = 0; i < 32; i += 8)
        out[(size_t)(c0 + ty + i) * 512 + r0 + tx] = __float2bfloat16_rn(t[tx][ty + i]);
}

// ---------------------------------------------------------------------------
// Kernel 1: GroupNorm (32 groups, eps=1e-6) -> g_hn [n][s][c] (bf16).
// Single global read: raw x staged into smt (transposed [s][c], stride 17)
// during the sum pass; pass 2 normalizes from smem and writes bf16.
// ---------------------------------------------------------------------------
__global__ void __launch_bounds__(256) gn_kernel(const float* __restrict__ x,
                                                 const float* __restrict__ sc,
                                                 const float* __restrict__ bi)
{
    extern __shared__ float smt[];   // [1024][17]
    int n = blockIdx.x >> 5;
    int g = blockIdx.x & 31;
    const float* px = x + (size_t)(n * Cc + g * 16) * Ss;
    bf16* ph = g_hn + (size_t)n * Ss * Cc + g * 16;
    int tid = threadIdx.x;
    const int M = 16 * Ss;

    float s = 0.f, ss = 0.f;
    for (int i = tid * 4; i < M; i += 1024) {
        int c  = i >> 10;
        int sp = i & 1023;
        float4 v = *(const float4*)&px[i];
        s  += v.x + v.y + v.z + v.w;
        ss += v.x*v.x + v.y*v.y + v.z*v.z + v.w*v.w;
        smt[(sp + 0) * 17 + c] = v.x;
        smt[(sp + 1) * 17 + c] = v.y;
        smt[(sp + 2) * 17 + c] = v.z;
        smt[(sp + 3) * 17 + c] = v.w;
    }
#pragma unroll
    for (int o = 16; o; o >>= 1) {
        s  += __shfl_xor_sync(0xffffffffu, s,  o);
        ss += __shfl_xor_sync(0xffffffffu, ss, o);
    }
    __shared__ float r0[8], r1[8];
    __shared__ float s_mean, s_inv;
    __shared__ float s_scv[16], s_biv[16];
    if ((tid & 31) == 0) { r0[tid >> 5] = s; r1[tid >> 5] = ss; }
    __syncthreads();
    if (tid == 0) {
        float a = 0.f, b2 = 0.f;
#pragma unroll
        for (int i = 0; i < 8; i++) { a += r0[i]; b2 += r1[i]; }
        float mean = a / (float)M;
        float var  = b2 / (float)M - mean * mean;
        s_mean = mean;
        s_inv  = rsqrtf(var + 1e-6f);
    }
    __syncthreads();
    if (tid < 16) {
        float scv = sc[g * 16 + tid] * s_inv;
        s_scv[tid] = scv;
        s_biv[tid] = bi[g * 16 + tid] - s_mean * scv;
    }
    __syncthreads();

    // pass 2: normalize from smem, pack bf16, write 32B rows
#pragma unroll
    for (int j = 0; j < 4; j++) {
        int sp = tid * 4 + j;
        const float* row = &smt[sp * 17];
        uint32_t pk[8];
#pragma unroll
        for (int q = 0; q < 8; q++)
            pk[q] = packbf(row[2*q]   * s_scv[2*q]   + s_biv[2*q],
                           row[2*q+1] * s_scv[2*q+1] + s_biv[2*q+1]);
        uint4* dst = (uint4*)(ph + (size_t)sp * Cc);
        dst[0] = make_uint4(pk[0], pk[1], pk[2], pk[3]);
        dst[1] = make_uint4(pk[4], pk[5], pk[6], pk[7]);
    }
}

// ---------------------------------------------------------------------------
// Kernel 2: bf16 m16n8k16 GEMM, tile 128x128, K=512, BK=32, 3-stage cp.async.
// 256 threads = 8 warps as 4(M) x 2(N); warp tile 32x64.  (R10 geometry —
// empirically at the mma.sync throughput ceiling.)
// SMEM: bf16, row stride 40 (80 B); stage = 20480 B, 3 stages = 61440 B.
// ---------------------------------------------------------------------------
__device__ __forceinline__ void gemm_load(uint32_t sbase, int soff,
                                          const bf16* __restrict__ Ag,
                                          const bf16* __restrict__ Bg,
                                          int koff, int tid)
{
#pragma unroll
    for (int i = 0; i < 2; i++) {
        int f = tid + i * 256;
        int row = f >> 2, c = f & 3;          // 4 x 16B chunks per 32-bf16 row
        cp16(sbase + (uint32_t)(soff + row * 80 + c * 16),
             Ag + (size_t)row * Cc + koff + c * 8);
        cp16(sbase + (uint32_t)(soff + 10240 + row * 80 + c * 16),
             Bg + (size_t)row * Cc + koff + c * 8);
    }
}

__global__ void __launch_bounds__(256, 2) gemm_mma(const float* __restrict__ bias,
                                                   const float* __restrict__ xres,
                                                   float* __restrict__ out,
                                                   int mode)
{
    extern __shared__ char smc[];
    uint32_t sbase = smem_u32(smc);
    int tid = threadIdx.x, lane = tid & 31, wid = tid >> 5;
    int g = lane >> 2, tg = lane & 3;
    int n = blockIdx.z, s0 = blockIdx.x * 128, d0 = blockIdx.y * 128;
    int wm = wid & 3, wn = wid >> 2;

    const bf16* Ag = (mode ? g_att : g_hn) + ((size_t)n * Ss + s0) * Cc;
    const bf16* Bg = (mode ? g_woutT : g_wqkvT) + (size_t)d0 * Cc;

    float C[2][8][4] = {};

    gemm_load(sbase, 0, Ag, Bg, 0, tid);
    CP_COMMIT();
    gemm_load(sbase, 20480, Ag, Bg, 32, tid);
    CP_COMMIT();

    for (int kc = 0; kc < 16; kc++) {
        CP_WAIT1();
        __syncthreads();
        int b = kc % 3;
        if (kc + 2 < 16)
            gemm_load(sbase, ((kc + 2) % 3) * 20480, Ag, Bg, (kc + 2) * 32, tid);
        CP_COMMIT();

        const bf16* As = (const bf16*)(smc + b * 20480);
        const bf16* Bs = (const bf16*)(smc + b * 20480 + 10240);
#pragma unroll
        for (int ks = 0; ks < 2; ks++) {       // two k16 steps per BK=32
            int k0 = ks * 16;
            uint32_t a[2][4], bb[8][2];
#pragma unroll
            for (int tm = 0; tm < 2; tm++) {
                int r = wm * 32 + tm * 16 + g;
                a[tm][0] = *(const uint32_t*)&As[r * 40 + k0 + 2 * tg];
                a[tm][1] = *(const uint32_t*)&As[(r + 8) * 40 + k0 + 2 * tg];
                a[tm][2] = *(const uint32_t*)&As[r * 40 + k0 + 2 * tg + 8];
                a[tm][3] = *(const uint32_t*)&As[(r + 8) * 40 + k0 + 2 * tg + 8];
            }
#pragma unroll
            for (int tn = 0; tn < 8; tn++) {
                int c = wn * 64 + tn * 8 + g;
                bb[tn][0] = *(const uint32_t*)&Bs[c * 40 + k0 + 2 * tg];
                bb[tn][1] = *(const uint32_t*)&Bs[c * 40 + k0 + 2 * tg + 8];
            }
#pragma unroll
            for (int tm = 0; tm < 2; tm++)
#pragma unroll
                for (int tn = 0; tn < 8; tn++)
                    mma16(C[tm][tn], a[tm], bb[tn]);
        }
    }

    // epilogue
#pragma unroll
    for (int tm = 0; tm < 2; tm++) {
#pragma unroll
        for (int hh = 0; hh < 2; hh++) {
            int m = s0 + wm * 32 + tm * 16 + g + hh * 8;
#pragma unroll
            for (int tn = 0; tn < 8; tn++) {
                int d = d0 + wn * 64 + tn * 8 + 2 * tg;
                float v0 = C[tm][tn][hh * 2 + 0] + __ldg(&bias[d]);
                float v1 = C[tm][tn][hh * 2 + 1] + __ldg(&bias[d + 1]);
                if (mode == 0) {
                    int head = d / 192, t = d % 192;
                    int part = t >> 6, e = t & 63;
                    size_t nh = (size_t)(n * 8 + head);
                    if (part == 0) {
                        *(uint32_t*)&g_q[(nh * Ss + m) * HD + e] = packbf(v0, v1);
                    } else if (part == 1) {
                        *(uint32_t*)&g_k[(nh * Ss + m) * HD + e] = packbf(v0, v1);
                    } else {
                        g_v[(nh * HD + e) * Ss + m]     = __float2bfloat16_rn(v0);
                        g_v[(nh * HD + e + 1) * Ss + m] = __float2bfloat16_rn(v1);
                    }
                } else {
                    size_t gi = ((size_t)n * Cc + d) * Ss + m;
                    out[gi]      = v0 + xres[gi];
                    out[gi + Ss] = v1 + xres[gi + Ss];
                }
            }
        }
    }
}

// ---------------------------------------------------------------------------
// Kernel 3: flash attention, bf16 m16n8k16, double-buffered cp.async K/V.
// 256 threads = 8 warps of 16 q rows, q-tile 128, 2 CTAs/SM.  (R10 verbatim.)
// P stays in registers (bf16 C-frag layout == A-frag layout, no shuffles).
// SMEM bytes: KV stage b: K at b*18432, V at +9216; Q at 36864. Total 55296.
// ---------------------------------------------------------------------------
#define ATT_SMEM 55296

__device__ __forceinline__ void attn_load_kv(uint32_t sbase, int b,
                                             const bf16* __restrict__ K,
                                             const bf16* __restrict__ V,
                                             int kt, int tid)
{
#pragma unroll
    for (int i = 0; i < 2; i++) {
        int f = tid + i * 256;
        int r = f >> 3, c = f & 7;            // 8 x 16B chunks per 64-bf16 row
        cp16(sbase + (uint32_t)(b * 18432 + r * 144 + c * 16),
             K + (size_t)(kt * 64 + r) * HD + c * 8);
        cp16(sbase + (uint32_t)(b * 18432 + 9216 + r * 144 + c * 16),
             V + (size_t)r * Ss + kt * 64 + c * 8);
    }
}

__global__ void __launch_bounds__(256, 2) attn_mma()
{
    extern __shared__ char smc[];
    uint32_t sbase = smem_u32(smc);
    const bf16* Qs = (const bf16*)(smc + 36864);

    int tid = threadIdx.x, lane = tid & 31, w = tid >> 5;
    int g = lane >> 2, tg = lane & 3;
    int nh = blockIdx.y, q0 = blockIdx.x * 128;
    const bf16* Q = g_q + (size_t)nh * Ss * HD;
    const bf16* K = g_k + (size_t)nh * Ss * HD;
    const bf16* V = g_v + (size_t)nh * HD * Ss;

    // prologue: Q + KV(0) -> group 0; KV(1) -> group 1
#pragma unroll
    for (int i = 0; i < 4; i++) {
        int f = tid + i * 256;
        int row = f >> 3, c = f & 7;
        cp16(sbase + (uint32_t)(36864 + row * 144 + c * 16),
             Q + (size_t)(q0 + row) * HD + c * 8);
    }
    attn_load_kv(sbase, 0, K, V, 0, tid);
    CP_COMMIT();
    attn_load_kv(sbase, 1, K, V, 1, tid);
    CP_COMMIT();

    float O[8][4] = {};
    float m0 = -1e30f, m1 = -1e30f, l0 = 0.f, l1 = 0.f;
    int qb = w * 16;

    for (int kt = 0; kt < 16; kt++) {
        CP_WAIT1();
        __syncthreads();
        int b = kt & 1;
        const bf16* Ks = (const bf16*)(smc + b * 18432);
        const bf16* Vs = (const bf16*)(smc + b * 18432 + 9216);

        // S = Q @ K^T  (warp: 16 q rows x 64 keys), k-dim = e: 4 k16 steps
        float S[8][4] = {};
#pragma unroll
        for (int ks = 0; ks < 4; ks++) {
            int k0 = ks * 16;
            uint32_t a[4];
            a[0] = *(const uint32_t*)&Qs[(qb + g) * 72 + k0 + 2 * tg];
            a[1] = *(const uint32_t*)&Qs[(qb + g + 8) * 72 + k0 + 2 * tg];
            a[2] = *(const uint32_t*)&Qs[(qb + g) * 72 + k0 + 2 * tg + 8];
            a[3] = *(const uint32_t*)&Qs[(qb + g + 8) * 72 + k0 + 2 * tg + 8];
#pragma unroll
            for (int tn = 0; tn < 8; tn++) {
                uint32_t bfr[2];
                bfr[0] = *(const uint32_t*)&Ks[(tn * 8 + g) * 72 + k0 + 2 * tg];
                bfr[1] = *(const uint32_t*)&Ks[(tn * 8 + g) * 72 + k0 + 2 * tg + 8];
                mma16(S[tn], a, bfr);
            }
        }

        // scale + online softmax
        float mx0 = -1e30f, mx1 = -1e30f;
#pragma unroll
        for (int tn = 0; tn < 8; tn++) {
            S[tn][0] *= 0.125f; S[tn][1] *= 0.125f;
            S[tn][2] *= 0.125f; S[tn][3] *= 0.125f;
            mx0 = fmaxf(mx0, fmaxf(S[tn][0], S[tn][1]));
            mx1 = fmaxf(mx1, fmaxf(S[tn][2], S[tn][3]));
        }
        mx0 = fmaxf(mx0, __shfl_xor_sync(0xffffffffu, mx0, 1));
        mx0 = fmaxf(mx0, __shfl_xor_sync(0xffffffffu, mx0, 2));
        mx1 = fmaxf(mx1, __shfl_xor_sync(0xffffffffu, mx1, 1));
        mx1 = fmaxf(mx1, __shfl_xor_sync(0xffffffffu, mx1, 2));
        float mn0 = fmaxf(m0, mx0), mn1 = fmaxf(m1, mx1);
        float cr0 = __expf(m0 - mn0), cr1 = __expf(m1 - mn1);
        float rs0 = 0.f, rs1 = 0.f;
        uint32_t Pp[8][2];
#pragma unroll
        for (int tn = 0; tn < 8; tn++) {
            S[tn][0] = __expf(S[tn][0] - mn0);
            S[tn][1] = __expf(S[tn][1] - mn0);
            S[tn][2] = __expf(S[tn][2] - mn1);
            S[tn][3] = __expf(S[tn][3] - mn1);
            rs0 += S[tn][0] + S[tn][1];
            rs1 += S[tn][2] + S[tn][3];
            Pp[tn][0] = packbf(S[tn][0], S[tn][1]);
            Pp[tn][1] = packbf(S[tn][2], S[tn][3]);
        }
        rs0 += __shfl_xor_sync(0xffffffffu, rs0, 1);
        rs0 += __shfl_xor_sync(0xffffffffu, rs0, 2);
        rs1 += __shfl_xor_sync(0xffffffffu, rs1, 1);
        rs1 += __shfl_xor_sync(0xffffffffu, rs1, 2);
        l0 = l0 * cr0 + rs0;  l1 = l1 * cr1 + rs1;
        m0 = mn0;  m1 = mn1;

#pragma unroll
        for (int tn = 0; tn < 8; tn++) {
            O[tn][0] *= cr0; O[tn][1] *= cr0;
            O[tn][2] *= cr1; O[tn][3] *= cr1;
        }

        // O += P @ V : 4 k16 steps over j (P from registers, no shuffles)
#pragma unroll
        for (int ks = 0; ks < 4; ks++) {
            int k0 = ks * 16;
            uint32_t a[4];
            a[0] = Pp[2 * ks][0];
            a[1] = Pp[2 * ks][1];
            a[2] = Pp[2 * ks + 1][0];
            a[3] = Pp[2 * ks + 1][1];
#pragma unroll
            for (int tn = 0; tn < 8; tn++) {
                uint32_t bfr[2];
                bfr[0] = *(const uint32_t*)&Vs[(tn * 8 + g) * 72 + k0 + 2 * tg];
                bfr[1] = *(const uint32_t*)&Vs[(tn * 8 + g) * 72 + k0 + 2 * tg + 8];
                mma16(O[tn], a, bfr);
            }
        }

        __syncthreads();
        if (kt + 2 < 16)
            attn_load_kv(sbase, b, K, V, kt + 2, tid);
        CP_COMMIT();
    }

    // epilogue -> g_att[n][s][head*64 + e] (bf16 pairs)
    int n = nh >> 3, head = nh & 7;
    float inv0 = 1.f / l0, inv1 = 1.f / l1;
    int srow0 = q0 + qb + g, srow1 = srow0 + 8;
    bf16* dst = g_att + (size_t)n * Ss * Cc + head * 64;
#pragma unroll
    for (int tn = 0; tn < 8; tn++) {
        int c = tn * 8 + 2 * tg;
        *(uint32_t*)&dst[(size_t)srow0 * Cc + c] = packbf(O[tn][0] * inv0, O[tn][1] * inv0);
        *(uint32_t*)&dst[(size_t)srow1 * Cc + c] = packbf(O[tn][2] * inv1, O[tn][3] * inv1);
    }
}

// ---------------------------------------------------------------------------
extern "C" void kernel_launch(void* const* d_in, const int* in_sizes, int n_in,
                              void* d_out, int out_size)
{
    const float* x    = (const float*)d_in[0];
    const float* gsc  = (const float*)d_in[1];
    const float* gbi  = (const float*)d_in[2];
    const float* wqkv = (const float*)d_in[3];
    const float* bqkv = (const float*)d_in[4];
    const float* wout = (const float*)d_in[5];
    const float* bout = (const float*)d_in[6];
    float* out = (float*)d_out;

    // both weight transposes in one launch
    trans_kernel<<<dim3(16, 16, 4), dim3(32, 8)>>>(wqkv, wout);

    // groupnorm (single global read; transposed bf16 output)
    cudaFuncSetAttribute(gn_kernel, cudaFuncAttributeMaxDynamicSharedMemorySize, 69632);
    gn_kernel<<<Nn * 32, 256, 69632>>>(x, gsc, gbi);

    const int gemm_smem = 61440;   // 3 stages x 20480 B
    cudaFuncSetAttribute(gemm_mma, cudaFuncAttributeMaxDynamicSharedMemorySize, gemm_smem);
    gemm_mma<<<dim3(Ss / 128, D3 / 128, Nn), 256, gemm_smem>>>(bqkv, nullptr, nullptr, 0);

    cudaFuncSetAttribute(attn_mma, cudaFuncAttributeMaxDynamicSharedMemorySize, ATT_SMEM);
    attn_mma<<<dim3(Ss / 128, Nn * NHEADS), 256, ATT_SMEM>>>();

    gemm_mma<<<dim3(Ss / 128, Cc / 128, Nn), 256, gemm_smem>>>(bout, x, out, 1);
}

// round 14
// speedup vs baseline: 1.1039x; 1.0216x over previous
#include <cuda_runtime.h>
#include <cuda_bf16.h>
#include <math.h>
#include <stdint.h>

// ---------------------------------------------------------------------------
// Problem constants
// ---------------------------------------------------------------------------
#define Nn 16            // B*T
#define Cc 512
#define Ss 1024          // H*W
#define NHEADS 8
#define HD 64
#define D3 1536          // 3*C

typedef __nv_bfloat16 bf16;

// ---------------------------------------------------------------------------
// Scratch (device globals; no cudaMalloc allowed)
// ---------------------------------------------------------------------------
__device__ bf16 g_hn   [Nn * Ss * Cc];           // [n][s][c]
__device__ bf16 g_q    [Nn * NHEADS * Ss * HD];  // [nh][s][e]
__device__ bf16 g_k    [Nn * NHEADS * Ss * HD];  // [nh][s][e]
__device__ bf16 g_v    [Nn * NHEADS * HD * Ss];  // [nh][e][s] (transposed)
__device__ bf16 g_att  [Nn * Ss * Cc];           // [n][s][c]
__device__ bf16 g_wqkvT[D3 * Cc];                // [d][c]
__device__ bf16 g_woutT[Cc * Cc];                // [c2][c]

// ---------------------------------------------------------------------------
// Helpers
// ---------------------------------------------------------------------------
__device__ __forceinline__ uint32_t smem_u32(const void* p) {
    uint32_t a;
    asm("{ .reg .u64 t; cvta.to.shared.u64 t, %1; cvt.u32.u64 %0, t; }"
        : "=r"(a) : "l"(p));
    return a;
}

// pack two fp32 -> bf16x2 (lo = first arg)
__device__ __forceinline__ uint32_t packbf(float lo, float hi) {
    uint32_t r;
    asm("cvt.rn.bf16x2.f32 %0, %1, %2;" : "=r"(r) : "f"(hi), "f"(lo));
    return r;
}

__device__ __forceinline__ float ex2(float x) {
    float r;
    asm("ex2.approx.f32 %0, %1;" : "=f"(r) : "f"(x));
    return r;
}

// m16n8k16 bf16 mma, D = A*B + D (in place), fp32 accumulate
__device__ __forceinline__ void mma16(float* d, const uint32_t* a, const uint32_t* b) {
    asm volatile(
        "mma.sync.aligned.m16n8k16.row.col.f32.bf16.bf16.f32 "
        "{%0,%1,%2,%3}, {%4,%5,%6,%7}, {%8,%9}, {%0,%1,%2,%3};"
        : "+f"(d[0]), "+f"(d[1]), "+f"(d[2]), "+f"(d[3])
        : "r"(a[0]), "r"(a[1]), "r"(a[2]), "r"(a[3]), "r"(b[0]), "r"(b[1]));
}

__device__ __forceinline__ void cp16(uint32_t dst, const void* src) {
    asm volatile("cp.async.cg.shared.global [%0], [%1], 16;" :: "r"(dst), "l"(src));
}
#define CP_COMMIT() asm volatile("cp.async.commit_group;" ::: "memory")
#define CP_WAIT1()  asm volatile("cp.async.wait_group 1;" ::: "memory")

// ---------------------------------------------------------------------------
// Kernel 0: both weight transposes + bf16 rounding in ONE launch.
// grid (16, 16, 4): z in 0..2 -> w_qkv column blocks; z == 3 -> w_out.
// ---------------------------------------------------------------------------
__global__ void __launch_bounds__(256) trans_kernel(const float* __restrict__ wqkv,
                                                    const float* __restrict__ wout)
{
    int z = blockIdx.z;
    const float* in = (z < 3) ? wqkv : wout;
    bf16* out       = (z < 3) ? g_wqkvT : g_woutT;
    int Ccols       = (z < 3) ? D3 : Cc;
    int c0 = ((z < 3) ? (z * 16 + blockIdx.x) : blockIdx.x) * 32;
    int r0 = blockIdx.y * 32;

    __shared__ float t[32][33];
    int tx = threadIdx.x, ty = threadIdx.y;
#pragma unroll
    for (int i = 0; i < 32; i += 8)
        t[ty + i][tx] = in[(size_t)(r0 + ty + i) * Ccols + c0 + tx];
    __syncthreads();
#pragma unroll
    for (int i = 0; i < 32; i += 8)
        out[(size_t)(c0 + ty + i) * 512 + r0 + tx] = __float2bfloat16_rn(t[tx][ty + i]);
}

// ---------------------------------------------------------------------------
// Kernel 1: GroupNorm (32 groups, eps=1e-6) -> g_hn [n][s][c] (bf16).
// Single global read: raw x staged into smt (transposed [s][c], stride 17).
// ---------------------------------------------------------------------------
__global__ void __launch_bounds__(256) gn_kernel(const float* __restrict__ x,
                                                 const float* __restrict__ sc,
                                                 const float* __restrict__ bi)
{
    extern __shared__ float smt[];   // [1024][17]
    int n = blockIdx.x >> 5;
    int g = blockIdx.x & 31;
    const float* px = x + (size_t)(n * Cc + g * 16) * Ss;
    bf16* ph = g_hn + (size_t)n * Ss * Cc + g * 16;
    int tid = threadIdx.x;
    const int M = 16 * Ss;

    float s = 0.f, ss = 0.f;
    for (int i = tid * 4; i < M; i += 1024) {
        int c  = i >> 10;
        int sp = i & 1023;
        float4 v = *(const float4*)&px[i];
        s  += v.x + v.y + v.z + v.w;
        ss += v.x*v.x + v.y*v.y + v.z*v.z + v.w*v.w;
        smt[(sp + 0) * 17 + c] = v.x;
        smt[(sp + 1) * 17 + c] = v.y;
        smt[(sp + 2) * 17 + c] = v.z;
        smt[(sp + 3) * 17 + c] = v.w;
    }
#pragma unroll
    for (int o = 16; o; o >>= 1) {
        s  += __shfl_xor_sync(0xffffffffu, s,  o);
        ss += __shfl_xor_sync(0xffffffffu, ss, o);
    }
    __shared__ float r0[8], r1[8];
    __shared__ float s_mean, s_inv;
    __shared__ float s_scv[16], s_biv[16];
    if ((tid & 31) == 0) { r0[tid >> 5] = s; r1[tid >> 5] = ss; }
    __syncthreads();
    if (tid == 0) {
        float a = 0.f, b2 = 0.f;
#pragma unroll
        for (int i = 0; i < 8; i++) { a += r0[i]; b2 += r1[i]; }
        float mean = a / (float)M;
        float var  = b2 / (float)M - mean * mean;
        s_mean = mean;
        s_inv  = rsqrtf(var + 1e-6f);
    }
    __syncthreads();
    if (tid < 16) {
        float scv = sc[g * 16 + tid] * s_inv;
        s_scv[tid] = scv;
        s_biv[tid] = bi[g * 16 + tid] - s_mean * scv;
    }
    __syncthreads();

#pragma unroll
    for (int j = 0; j < 4; j++) {
        int sp = tid * 4 + j;
        const float* row = &smt[sp * 17];
        uint32_t pk[8];
#pragma unroll
        for (int q = 0; q < 8; q++)
            pk[q] = packbf(row[2*q]   * s_scv[2*q]   + s_biv[2*q],
                           row[2*q+1] * s_scv[2*q+1] + s_biv[2*q+1]);
        uint4* dst = (uint4*)(ph + (size_t)sp * Cc);
        dst[0] = make_uint4(pk[0], pk[1], pk[2], pk[3]);
        dst[1] = make_uint4(pk[4], pk[5], pk[6], pk[7]);
    }
}

// ---------------------------------------------------------------------------
// Kernel 2: bf16 m16n8k16 GEMM, tile 128x128, K=512, BK=32, 3-stage cp.async.
// 256 threads = 8 warps as 4(M) x 2(N); warp tile 32x64.  (R10/R13 geometry.)
// ---------------------------------------------------------------------------
__device__ __forceinline__ void gemm_load(uint32_t sbase, int soff,
                                          const bf16* __restrict__ Ag,
                                          const bf16* __restrict__ Bg,
                                          int koff, int tid)
{
#pragma unroll
    for (int i = 0; i < 2; i++) {
        int f = tid + i * 256;
        int row = f >> 2, c = f & 3;
        cp16(sbase + (uint32_t)(soff + row * 80 + c * 16),
             Ag + (size_t)row * Cc + koff + c * 8);
        cp16(sbase + (uint32_t)(soff + 10240 + row * 80 + c * 16),
             Bg + (size_t)row * Cc + koff + c * 8);
    }
}

__global__ void __launch_bounds__(256, 2) gemm_mma(const float* __restrict__ bias,
                                                   const float* __restrict__ xres,
                                                   float* __restrict__ out,
                                                   int mode)
{
    extern __shared__ char smc[];
    uint32_t sbase = smem_u32(smc);
    int tid = threadIdx.x, lane = tid & 31, wid = tid >> 5;
    int g = lane >> 2, tg = lane & 3;
    int n = blockIdx.z, s0 = blockIdx.x * 128, d0 = blockIdx.y * 128;
    int wm = wid & 3, wn = wid >> 2;

    const bf16* Ag = (mode ? g_att : g_hn) + ((size_t)n * Ss + s0) * Cc;
    const bf16* Bg = (mode ? g_woutT : g_wqkvT) + (size_t)d0 * Cc;

    float C[2][8][4] = {};

    gemm_load(sbase, 0, Ag, Bg, 0, tid);
    CP_COMMIT();
    gemm_load(sbase, 20480, Ag, Bg, 32, tid);
    CP_COMMIT();

    for (int kc = 0; kc < 16; kc++) {
        CP_WAIT1();
        __syncthreads();
        int b = kc % 3;
        if (kc + 2 < 16)
            gemm_load(sbase, ((kc + 2) % 3) * 20480, Ag, Bg, (kc + 2) * 32, tid);
        CP_COMMIT();

        const bf16* As = (const bf16*)(smc + b * 20480);
        const bf16* Bs = (const bf16*)(smc + b * 20480 + 10240);
#pragma unroll
        for (int ks = 0; ks < 2; ks++) {
            int k0 = ks * 16;
            uint32_t a[2][4], bb[8][2];
#pragma unroll
            for (int tm = 0; tm < 2; tm++) {
                int r = wm * 32 + tm * 16 + g;
                a[tm][0] = *(const uint32_t*)&As[r * 40 + k0 + 2 * tg];
                a[tm][1] = *(const uint32_t*)&As[(r + 8) * 40 + k0 + 2 * tg];
                a[tm][2] = *(const uint32_t*)&As[r * 40 + k0 + 2 * tg + 8];
                a[tm][3] = *(const uint32_t*)&As[(r + 8) * 40 + k0 + 2 * tg + 8];
            }
#pragma unroll
            for (int tn = 0; tn < 8; tn++) {
                int c = wn * 64 + tn * 8 + g;
                bb[tn][0] = *(const uint32_t*)&Bs[c * 40 + k0 + 2 * tg];
                bb[tn][1] = *(const uint32_t*)&Bs[c * 40 + k0 + 2 * tg + 8];
            }
#pragma unroll
            for (int tm = 0; tm < 2; tm++)
#pragma unroll
                for (int tn = 0; tn < 8; tn++)
                    mma16(C[tm][tn], a[tm], bb[tn]);
        }
    }

    // epilogue
#pragma unroll
    for (int tm = 0; tm < 2; tm++) {
#pragma unroll
        for (int hh = 0; hh < 2; hh++) {
            int m = s0 + wm * 32 + tm * 16 + g + hh * 8;
#pragma unroll
            for (int tn = 0; tn < 8; tn++) {
                int d = d0 + wn * 64 + tn * 8 + 2 * tg;
                float v0 = C[tm][tn][hh * 2 + 0] + __ldg(&bias[d]);
                float v1 = C[tm][tn][hh * 2 + 1] + __ldg(&bias[d + 1]);
                if (mode == 0) {
                    int head = d / 192, t = d % 192;
                    int part = t >> 6, e = t & 63;
                    size_t nh = (size_t)(n * 8 + head);
                    if (part == 0) {
                        *(uint32_t*)&g_q[(nh * Ss + m) * HD + e] = packbf(v0, v1);
                    } else if (part == 1) {
                        *(uint32_t*)&g_k[(nh * Ss + m) * HD + e] = packbf(v0, v1);
                    } else {
                        g_v[(nh * HD + e) * Ss + m]     = __float2bfloat16_rn(v0);
                        g_v[(nh * HD + e + 1) * Ss + m] = __float2bfloat16_rn(v1);
                    }
                } else {
                    size_t gi = ((size_t)n * Cc + d) * Ss + m;
                    out[gi]      = v0 + xres[gi];
                    out[gi + Ss] = v1 + xres[gi + Ss];
                }
            }
        }
    }
}

// ---------------------------------------------------------------------------
// Kernel 3: flash attention, bf16 m16n8k16, double-buffered cp.async K/V.
// exp2-domain softmax: c = 0.125*log2(e) folded into one FFMA per element;
// running max tracked in the log2 domain (identical math, fewer scalar ops).
// ---------------------------------------------------------------------------
#define ATT_SMEM 55296
#define CSCALE 0.18033688f   // 0.125 * log2(e)

__device__ __forceinline__ void attn_load_kv(uint32_t sbase, int b,
                                             const bf16* __restrict__ K,
                                             const bf16* __restrict__ V,
                                             int kt, int tid)
{
#pragma unroll
    for (int i = 0; i < 2; i++) {
        int f = tid + i * 256;
        int r = f >> 3, c = f & 7;
        cp16(sbase + (uint32_t)(b * 18432 + r * 144 + c * 16),
             K + (size_t)(kt * 64 + r) * HD + c * 8);
        cp16(sbase + (uint32_t)(b * 18432 + 9216 + r * 144 + c * 16),
             V + (size_t)r * Ss + kt * 64 + c * 8);
    }
}

__global__ void __launch_bounds__(256, 2) attn_mma()
{
    extern __shared__ char smc[];
    uint32_t sbase = smem_u32(smc);
    const bf16* Qs = (const bf16*)(smc + 36864);

    int tid = threadIdx.x, lane = tid & 31, w = tid >> 5;
    int g = lane >> 2, tg = lane & 3;
    int nh = blockIdx.y, q0 = blockIdx.x * 128;
    const bf16* Q = g_q + (size_t)nh * Ss * HD;
    const bf16* K = g_k + (size_t)nh * Ss * HD;
    const bf16* V = g_v + (size_t)nh * HD * Ss;

#pragma unroll
    for (int i = 0; i < 4; i++) {
        int f = tid + i * 256;
        int row = f >> 3, c = f & 7;
        cp16(sbase + (uint32_t)(36864 + row * 144 + c * 16),
             Q + (size_t)(q0 + row) * HD + c * 8);
    }
    attn_load_kv(sbase, 0, K, V, 0, tid);
    CP_COMMIT();
    attn_load_kv(sbase, 1, K, V, 1, tid);
    CP_COMMIT();

    float O[8][4] = {};
    float m0 = -1e30f, m1 = -1e30f, l0 = 0.f, l1 = 0.f;  // m in log2 domain
    int qb = w * 16;

    for (int kt = 0; kt < 16; kt++) {
        CP_WAIT1();
        __syncthreads();
        int b = kt & 1;
        const bf16* Ks = (const bf16*)(smc + b * 18432);
        const bf16* Vs = (const bf16*)(smc + b * 18432 + 9216);

        // S = Q @ K^T  (warp: 16 q rows x 64 keys), k-dim = e: 4 k16 steps
        float S[8][4] = {};
#pragma unroll
        for (int ks = 0; ks < 4; ks++) {
            int k0 = ks * 16;
            uint32_t a[4];
            a[0] = *(const uint32_t*)&Qs[(qb + g) * 72 + k0 + 2 * tg];
            a[1] = *(const uint32_t*)&Qs[(qb + g + 8) * 72 + k0 + 2 * tg];
            a[2] = *(const uint32_t*)&Qs[(qb + g) * 72 + k0 + 2 * tg + 8];
            a[3] = *(const uint32_t*)&Qs[(qb + g + 8) * 72 + k0 + 2 * tg + 8];
#pragma unroll
            for (int tn = 0; tn < 8; tn++) {
                uint32_t bfr[2];
                bfr[0] = *(const uint32_t*)&Ks[(tn * 8 + g) * 72 + k0 + 2 * tg];
                bfr[1] = *(const uint32_t*)&Ks[(tn * 8 + g) * 72 + k0 + 2 * tg + 8];
                mma16(S[tn], a, bfr);
            }
        }

        // online softmax in exp2 domain: max over RAW S, then one FFMA+EX2/elem
        float mx0 = -1e30f, mx1 = -1e30f;
#pragma unroll
        for (int tn = 0; tn < 8; tn++) {
            mx0 = fmaxf(mx0, fmaxf(S[tn][0], S[tn][1]));
            mx1 = fmaxf(mx1, fmaxf(S[tn][2], S[tn][3]));
        }
        mx0 = fmaxf(mx0, __shfl_xor_sync(0xffffffffu, mx0, 1));
        mx0 = fmaxf(mx0, __shfl_xor_sync(0xffffffffu, mx0, 2));
        mx1 = fmaxf(mx1, __shfl_xor_sync(0xffffffffu, mx1, 1));
        mx1 = fmaxf(mx1, __shfl_xor_sync(0xffffffffu, mx1, 2));
        float mn0 = fmaxf(m0, mx0 * CSCALE), mn1 = fmaxf(m1, mx1 * CSCALE);
        float cr0 = ex2(m0 - mn0), cr1 = ex2(m1 - mn1);
        float rs0 = 0.f, rs1 = 0.f;
        uint32_t Pp[8][2];
#pragma unroll
        for (int tn = 0; tn < 8; tn++) {
            float p0 = ex2(fmaf(S[tn][0], CSCALE, -mn0));
            float p1 = ex2(fmaf(S[tn][1], CSCALE, -mn0));
            float p2 = ex2(fmaf(S[tn][2], CSCALE, -mn1));
            float p3 = ex2(fmaf(S[tn][3], CSCALE, -mn1));
            rs0 += p0 + p1;
            rs1 += p2 + p3;
            Pp[tn][0] = packbf(p0, p1);
            Pp[tn][1] = packbf(p2, p3);
        }
        rs0 += __shfl_xor_sync(0xffffffffu, rs0, 1);
        rs0 += __shfl_xor_sync(0xffffffffu, rs0, 2);
        rs1 += __shfl_xor_sync(0xffffffffu, rs1, 1);
        rs1 += __shfl_xor_sync(0xffffffffu, rs1, 2);
        l0 = l0 * cr0 + rs0;  l1 = l1 * cr1 + rs1;
        m0 = mn0;  m1 = mn1;

#pragma unroll
        for (int tn = 0; tn < 8; tn++) {
            O[tn][0] *= cr0; O[tn][1] *= cr0;
            O[tn][2] *= cr1; O[tn][3] *= cr1;
        }

        // O += P @ V : 4 k16 steps over j (P from registers, no shuffles)
#pragma unroll
        for (int ks = 0; ks < 4; ks++) {
            int k0 = ks * 16;
            uint32_t a[4];
            a[0] = Pp[2 * ks][0];
            a[1] = Pp[2 * ks][1];
            a[2] = Pp[2 * ks + 1][0];
            a[3] = Pp[2 * ks + 1][1];
#pragma unroll
            for (int tn = 0; tn < 8; tn++) {
                uint32_t bfr[2];
                bfr[0] = *(const uint32_t*)&Vs[(tn * 8 + g) * 72 + k0 + 2 * tg];
                bfr[1] = *(const uint32_t*)&Vs[(tn * 8 + g) * 72 + k0 + 2 * tg + 8];
                mma16(O[tn], a, bfr);
            }
        }

        __syncthreads();
        if (kt + 2 < 16)
            attn_load_kv(sbase, b, K, V, kt + 2, tid);
        CP_COMMIT();
    }

    // epilogue -> g_att[n][s][head*64 + e] (bf16 pairs)
    int n = nh >> 3, head = nh & 7;
    float inv0 = 1.f / l0, inv1 = 1.f / l1;
    int srow0 = q0 + qb + g, srow1 = srow0 + 8;
    bf16* dst = g_att + (size_t)n * Ss * Cc + head * 64;
#pragma unroll
    for (int tn = 0; tn < 8; tn++) {
        int c = tn * 8 + 2 * tg;
        *(uint32_t*)&dst[(size_t)srow0 * Cc + c] = packbf(O[tn][0] * inv0, O[tn][1] * inv0);
        *(uint32_t*)&dst[(size_t)srow1 * Cc + c] = packbf(O[tn][2] * inv1, O[tn][3] * inv1);
    }
}

// ---------------------------------------------------------------------------
extern "C" void kernel_launch(void* const* d_in, const int* in_sizes, int n_in,
                              void* d_out, int out_size)
{
    const float* x    = (const float*)d_in[0];
    const float* gsc  = (const float*)d_in[1];
    const float* gbi  = (const float*)d_in[2];
    const float* wqkv = (const float*)d_in[3];
    const float* bqkv = (const float*)d_in[4];
    const float* wout = (const float*)d_in[5];
    const float* bout = (const float*)d_in[6];
    float* out = (float*)d_out;

    trans_kernel<<<dim3(16, 16, 4), dim3(32, 8)>>>(wqkv, wout);

    cudaFuncSetAttribute(gn_kernel, cudaFuncAttributeMaxDynamicSharedMemorySize, 69632);
    gn_kernel<<<Nn * 32, 256, 69632>>>(x, gsc, gbi);

    const int gemm_smem = 61440;
    cudaFuncSetAttribute(gemm_mma, cudaFuncAttributeMaxDynamicSharedMemorySize, gemm_smem);
    gemm_mma<<<dim3(Ss / 128, D3 / 128, Nn), 256, gemm_smem>>>(bqkv, nullptr, nullptr, 0);

    cudaFuncSetAttribute(attn_mma, cudaFuncAttributeMaxDynamicSharedMemorySize, ATT_SMEM);
    attn_mma<<<dim3(Ss / 128, Nn * NHEADS), 256, ATT_SMEM>>>();

    gemm_mma<<<dim3(Ss / 128, Cc / 128, Nn), 256, gemm_smem>>>(bout, x, out, 1);
}

// round 15
// speedup vs baseline: 1.1186x; 1.0134x over previous
#include <cuda_runtime.h>
#include <cuda_bf16.h>
#include <math.h>
#include <stdint.h>

// ---------------------------------------------------------------------------
// Problem constants
// ---------------------------------------------------------------------------
#define Nn 16            // B*T
#define Cc 512
#define Ss 1024          // H*W
#define NHEADS 8
#define HD 64
#define D3 1536          // 3*C

typedef __nv_bfloat16 bf16;

// ---------------------------------------------------------------------------
// Scratch (device globals; no cudaMalloc allowed)
// q/k: e-dim permuted within 16-groups; v: s-dim permuted within 16-groups
// (fragment-order layout: orig {2t,2t+1,2t+8,2t+9} -> positions {4t..4t+3})
// ---------------------------------------------------------------------------
__device__ bf16 g_hn   [Nn * Ss * Cc];           // [n][s][c]
__device__ bf16 g_q    [Nn * NHEADS * Ss * HD];  // [nh][s][e-perm]
__device__ bf16 g_k    [Nn * NHEADS * Ss * HD];  // [nh][s][e-perm]
__device__ bf16 g_v    [Nn * NHEADS * HD * Ss];  // [nh][e][s-perm]
__device__ bf16 g_att  [Nn * Ss * Cc];           // [n][s][c]
__device__ bf16 g_wqkvT[D3 * Cc];                // [d][c]
__device__ bf16 g_woutT[Cc * Cc];                // [c2][c]

// ---------------------------------------------------------------------------
// Helpers
// ---------------------------------------------------------------------------
__device__ __forceinline__ uint32_t smem_u32(const void* p) {
    uint32_t a;
    asm("{ .reg .u64 t; cvta.to.shared.u64 t, %1; cvt.u32.u64 %0, t; }"
        : "=r"(a) : "l"(p));
    return a;
}

// pack two fp32 -> bf16x2 (lo = first arg)
__device__ __forceinline__ uint32_t packbf(float lo, float hi) {
    uint32_t r;
    asm("cvt.rn.bf16x2.f32 %0, %1, %2;" : "=r"(r) : "f"(hi), "f"(lo));
    return r;
}

__device__ __forceinline__ float ex2(float x) {
    float r;
    asm("ex2.approx.f32 %0, %1;" : "=f"(r) : "f"(x));
    return r;
}

// m16n8k16 bf16 mma, D = A*B + D (in place), fp32 accumulate
__device__ __forceinline__ void mma16(float* d, const uint32_t* a, const uint32_t* b) {
    asm volatile(
        "mma.sync.aligned.m16n8k16.row.col.f32.bf16.bf16.f32 "
        "{%0,%1,%2,%3}, {%4,%5,%6,%7}, {%8,%9}, {%0,%1,%2,%3};"
        : "+f"(d[0]), "+f"(d[1]), "+f"(d[2]), "+f"(d[3])
        : "r"(a[0]), "r"(a[1]), "r"(a[2]), "r"(a[3]), "r"(b[0]), "r"(b[1]));
}

// 8-byte shared load straight into two operand registers (no repack)
__device__ __forceinline__ void lds64(uint32_t& r0, uint32_t& r1, uint32_t addr) {
    asm volatile("ld.shared.v2.u32 {%0,%1}, [%2];" : "=r"(r0), "=r"(r1) : "r"(addr));
}

__device__ __forceinline__ void cp16(uint32_t dst, const void* src) {
    asm volatile("cp.async.cg.shared.global [%0], [%1], 16;" :: "r"(dst), "l"(src));
}
#define CP_COMMIT() asm volatile("cp.async.commit_group;" ::: "memory")
#define CP_WAIT1()  asm volatile("cp.async.wait_group 1;" ::: "memory")

// ---------------------------------------------------------------------------
// Kernel 0: both weight transposes + bf16 rounding in ONE launch.
// ---------------------------------------------------------------------------
__global__ void __launch_bounds__(256) trans_kernel(const float* __restrict__ wqkv,
                                                    const float* __restrict__ wout)
{
    int z = blockIdx.z;
    const float* in = (z < 3) ? wqkv : wout;
    bf16* out       = (z < 3) ? g_wqkvT : g_woutT;
    int Ccols       = (z < 3) ? D3 : Cc;
    int c0 = ((z < 3) ? (z * 16 + blockIdx.x) : blockIdx.x) * 32;
    int r0 = blockIdx.y * 32;

    __shared__ float t[32][33];
    int tx = threadIdx.x, ty = threadIdx.y;
#pragma unroll
    for (int i = 0; i < 32; i += 8)
        t[ty + i][tx] = in[(size_t)(r0 + ty + i) * Ccols + c0 + tx];
    __syncthreads();
#pragma unroll
    for (int i = 0; i < 32; i += 8)
        out[(size_t)(c0 + ty + i) * 512 + r0 + tx] = __float2bfloat16_rn(t[tx][ty + i]);
}

// ---------------------------------------------------------------------------
// Kernel 1: GroupNorm (32 groups, eps=1e-6) -> g_hn [n][s][c] (bf16).
// ---------------------------------------------------------------------------
__global__ void __launch_bounds__(256) gn_kernel(const float* __restrict__ x,
                                                 const float* __restrict__ sc,
                                                 const float* __restrict__ bi)
{
    extern __shared__ float smt[];   // [1024][17]
    int n = blockIdx.x >> 5;
    int g = blockIdx.x & 31;
    const float* px = x + (size_t)(n * Cc + g * 16) * Ss;
    bf16* ph = g_hn + (size_t)n * Ss * Cc + g * 16;
    int tid = threadIdx.x;
    const int M = 16 * Ss;

    float s = 0.f, ss = 0.f;
    for (int i = tid * 4; i < M; i += 1024) {
        int c  = i >> 10;
        int sp = i & 1023;
        float4 v = *(const float4*)&px[i];
        s  += v.x + v.y + v.z + v.w;
        ss += v.x*v.x + v.y*v.y + v.z*v.z + v.w*v.w;
        smt[(sp + 0) * 17 + c] = v.x;
        smt[(sp + 1) * 17 + c] = v.y;
        smt[(sp + 2) * 17 + c] = v.z;
        smt[(sp + 3) * 17 + c] = v.w;
    }
#pragma unroll
    for (int o = 16; o; o >>= 1) {
        s  += __shfl_xor_sync(0xffffffffu, s,  o);
        ss += __shfl_xor_sync(0xffffffffu, ss, o);
    }
    __shared__ float r0[8], r1[8];
    __shared__ float s_mean, s_inv;
    __shared__ float s_scv[16], s_biv[16];
    if ((tid & 31) == 0) { r0[tid >> 5] = s; r1[tid >> 5] = ss; }
    __syncthreads();
    if (tid == 0) {
        float a = 0.f, b2 = 0.f;
#pragma unroll
        for (int i = 0; i < 8; i++) { a += r0[i]; b2 += r1[i]; }
        float mean = a / (float)M;
        float var  = b2 / (float)M - mean * mean;
        s_mean = mean;
        s_inv  = rsqrtf(var + 1e-6f);
    }
    __syncthreads();
    if (tid < 16) {
        float scv = sc[g * 16 + tid] * s_inv;
        s_scv[tid] = scv;
        s_biv[tid] = bi[g * 16 + tid] - s_mean * scv;
    }
    __syncthreads();

#pragma unroll
    for (int j = 0; j < 4; j++) {
        int sp = tid * 4 + j;
        const float* row = &smt[sp * 17];
        uint32_t pk[8];
#pragma unroll
        for (int q = 0; q < 8; q++)
            pk[q] = packbf(row[2*q]   * s_scv[2*q]   + s_biv[2*q],
                           row[2*q+1] * s_scv[2*q+1] + s_biv[2*q+1]);
        uint4* dst = (uint4*)(ph + (size_t)sp * Cc);
        dst[0] = make_uint4(pk[0], pk[1], pk[2], pk[3]);
        dst[1] = make_uint4(pk[4], pk[5], pk[6], pk[7]);
    }
}

// ---------------------------------------------------------------------------
// Kernel 2: bf16 m16n8k16 GEMM, tile 128x128, K=512, BK=32, 3-stage cp.async.
// 256 threads = 8 warps as 4(M) x 2(N); warp tile 32x64.  (R13 geometry.)
// mode 0 epilogue writes q/k with e-perm, v with s-perm (fragment order).
// ---------------------------------------------------------------------------
__device__ __forceinline__ void gemm_load(uint32_t sbase, int soff,
                                          const bf16* __restrict__ Ag,
                                          const bf16* __restrict__ Bg,
                                          int koff, int tid)
{
#pragma unroll
    for (int i = 0; i < 2; i++) {
        int f = tid + i * 256;
        int row = f >> 2, c = f & 3;
        cp16(sbase + (uint32_t)(soff + row * 80 + c * 16),
             Ag + (size_t)row * Cc + koff + c * 8);
        cp16(sbase + (uint32_t)(soff + 10240 + row * 80 + c * 16),
             Bg + (size_t)row * Cc + koff + c * 8);
    }
}

__global__ void __launch_bounds__(256, 2) gemm_mma(const float* __restrict__ bias,
                                                   const float* __restrict__ xres,
                                                   float* __restrict__ out,
                                                   int mode)
{
    extern __shared__ char smc[];
    uint32_t sbase = smem_u32(smc);
    int tid = threadIdx.x, lane = tid & 31, wid = tid >> 5;
    int g = lane >> 2, tg = lane & 3;
    int n = blockIdx.z, s0 = blockIdx.x * 128, d0 = blockIdx.y * 128;
    int wm = wid & 3, wn = wid >> 2;

    const bf16* Ag = (mode ? g_att : g_hn) + ((size_t)n * Ss + s0) * Cc;
    const bf16* Bg = (mode ? g_woutT : g_wqkvT) + (size_t)d0 * Cc;

    float C[2][8][4] = {};

    gemm_load(sbase, 0, Ag, Bg, 0, tid);
    CP_COMMIT();
    gemm_load(sbase, 20480, Ag, Bg, 32, tid);
    CP_COMMIT();

    for (int kc = 0; kc < 16; kc++) {
        CP_WAIT1();
        __syncthreads();
        int b = kc % 3;
        if (kc + 2 < 16)
            gemm_load(sbase, ((kc + 2) % 3) * 20480, Ag, Bg, (kc + 2) * 32, tid);
        CP_COMMIT();

        const bf16* As = (const bf16*)(smc + b * 20480);
        const bf16* Bs = (const bf16*)(smc + b * 20480 + 10240);
#pragma unroll
        for (int ks = 0; ks < 2; ks++) {
            int k0 = ks * 16;
            uint32_t a[2][4], bb[8][2];
#pragma unroll
            for (int tm = 0; tm < 2; tm++) {
                int r = wm * 32 + tm * 16 + g;
                a[tm][0] = *(const uint32_t*)&As[r * 40 + k0 + 2 * tg];
                a[tm][1] = *(const uint32_t*)&As[(r + 8) * 40 + k0 + 2 * tg];
                a[tm][2] = *(const uint32_t*)&As[r * 40 + k0 + 2 * tg + 8];
                a[tm][3] = *(const uint32_t*)&As[(r + 8) * 40 + k0 + 2 * tg + 8];
            }
#pragma unroll
            for (int tn = 0; tn < 8; tn++) {
                int c = wn * 64 + tn * 8 + g;
                bb[tn][0] = *(const uint32_t*)&Bs[c * 40 + k0 + 2 * tg];
                bb[tn][1] = *(const uint32_t*)&Bs[c * 40 + k0 + 2 * tg + 8];
            }
#pragma unroll
            for (int tm = 0; tm < 2; tm++)
#pragma unroll
                for (int tn = 0; tn < 8; tn++)
                    mma16(C[tm][tn], a[tm], bb[tn]);
        }
    }

    // epilogue
#pragma unroll
    for (int tm = 0; tm < 2; tm++) {
#pragma unroll
        for (int hh = 0; hh < 2; hh++) {
            int m = s0 + wm * 32 + tm * 16 + g + hh * 8;
#pragma unroll
            for (int tn = 0; tn < 8; tn++) {
                int d = d0 + wn * 64 + tn * 8 + 2 * tg;
                float v0 = C[tm][tn][hh * 2 + 0] + __ldg(&bias[d]);
                float v1 = C[tm][tn][hh * 2 + 1] + __ldg(&bias[d + 1]);
                if (mode == 0) {
                    int head = d / 192, t = d % 192;
                    int part = t >> 6, e = t & 63;
                    size_t nh = (size_t)(n * 8 + head);
                    if (part < 2) {
                        // e-perm: orig pair (e,e+1), e even -> adjacent slot
                        int eg = e & 15;
                        int ep = (e & ~15) + ((eg >> 1) & 3) * 4 + (eg >> 3) * 2;
                        bf16* dst = part == 0 ? g_q : g_k;
                        *(uint32_t*)&dst[(nh * Ss + m) * HD + ep] = packbf(v0, v1);
                    } else {
                        // s-perm for v rows
                        int mg = m & 15;
                        int mp = (m & ~15) + ((mg >> 1) & 3) * 4 + (mg >> 3) * 2 + (mg & 1);
                        g_v[(nh * HD + e) * Ss + mp]     = __float2bfloat16_rn(v0);
                        g_v[(nh * HD + e + 1) * Ss + mp] = __float2bfloat16_rn(v1);
                    }
                } else {
                    size_t gi = ((size_t)n * Cc + d) * Ss + m;
                    out[gi]      = v0 + xres[gi];
                    out[gi + Ss] = v1 + xres[gi + Ss];
                }
            }
        }
    }
}

// ---------------------------------------------------------------------------
// Kernel 3: flash attention, bf16 m16n8k16, double-buffered cp.async K/V.
// Fragment-order permuted k-dims -> every fragment is ONE ld.shared.v2.u32
// (144 LDS.32 -> 72 LDS.64 per warp-tile, zero repack).
// SMEM rows 80 bf16 (160 B, 40 words === 8 mod 32 -> conflict-free LDS.64).
// Layout: stage b: K at b*20480, V at +10240; Q at 40960. Total 61440 B.
// ---------------------------------------------------------------------------
#define ATT_SMEM 61440
#define CSCALE 0.18033688f   // 0.125 * log2(e)

__device__ __forceinline__ void attn_load_kv(uint32_t sbase, int b,
                                             const bf16* __restrict__ K,
                                             const bf16* __restrict__ V,
                                             int kt, int tid)
{
#pragma unroll
    for (int i = 0; i < 2; i++) {
        int f = tid + i * 256;
        int r = f >> 3, c = f & 7;            // 8 x 16B chunks per 64-bf16 row
        cp16(sbase + (uint32_t)(b * 20480 + r * 160 + c * 16),
             K + (size_t)(kt * 64 + r) * HD + c * 8);
        cp16(sbase + (uint32_t)(b * 20480 + 10240 + r * 160 + c * 16),
             V + (size_t)r * Ss + kt * 64 + c * 8);
    }
}

__global__ void __launch_bounds__(256, 2) attn_mma()
{
    extern __shared__ char smc[];
    uint32_t sbase = smem_u32(smc);

    int tid = threadIdx.x, lane = tid & 31, w = tid >> 5;
    int g = lane >> 2, tg = lane & 3;
    int nh = blockIdx.y, q0 = blockIdx.x * 128;
    const bf16* Q = g_q + (size_t)nh * Ss * HD;
    const bf16* K = g_k + (size_t)nh * Ss * HD;
    const bf16* V = g_v + (size_t)nh * HD * Ss;

    // prologue: Q + KV(0) -> group 0; KV(1) -> group 1
#pragma unroll
    for (int i = 0; i < 4; i++) {
        int f = tid + i * 256;
        int row = f >> 3, c = f & 7;
        cp16(sbase + (uint32_t)(40960 + row * 160 + c * 16),
             Q + (size_t)(q0 + row) * HD + c * 8);
    }
    attn_load_kv(sbase, 0, K, V, 0, tid);
    CP_COMMIT();
    attn_load_kv(sbase, 1, K, V, 1, tid);
    CP_COMMIT();

    float O[8][4] = {};
    float m0 = -1e30f, m1 = -1e30f, l0 = 0.f, l1 = 0.f;  // m in log2 domain
    int qb = w * 16;

    // per-lane row base addresses (byte offsets; fragment col = ks*32 + tg*8)
    uint32_t qRow0 = sbase + 40960u + (uint32_t)((qb + g) * 160) + (uint32_t)(tg * 8);
    uint32_t qRow1 = qRow0 + 8 * 160;

    for (int kt = 0; kt < 16; kt++) {
        CP_WAIT1();
        __syncthreads();
        int b = kt & 1;
        uint32_t kBase = sbase + (uint32_t)(b * 20480) + (uint32_t)(g * 160) + (uint32_t)(tg * 8);
        uint32_t vBase = kBase + 10240u;

        // S = Q @ K^T  (warp: 16 q rows x 64 keys), 4 k16 steps, LDS.64 frags
        float S[8][4] = {};
#pragma unroll
        for (int ks = 0; ks < 4; ks++) {
            uint32_t co = (uint32_t)(ks * 32);
            uint32_t a[4];
            lds64(a[0], a[2], qRow0 + co);
            lds64(a[1], a[3], qRow1 + co);
#pragma unroll
            for (int tn = 0; tn < 8; tn++) {
                uint32_t bfr[2];
                lds64(bfr[0], bfr[1], kBase + (uint32_t)(tn * 8 * 160) + co);
                mma16(S[tn], a, bfr);
            }
        }

        // online softmax in exp2 domain
        float mx0 = -1e30f, mx1 = -1e30f;
#pragma unroll
        for (int tn = 0; tn < 8; tn++) {
            mx0 = fmaxf(mx0, fmaxf(S[tn][0], S[tn][1]));
            mx1 = fmaxf(mx1, fmaxf(S[tn][2], S[tn][3]));
        }
        mx0 = fmaxf(mx0, __shfl_xor_sync(0xffffffffu, mx0, 1));
        mx0 = fmaxf(mx0, __shfl_xor_sync(0xffffffffu, mx0, 2));
        mx1 = fmaxf(mx1, __shfl_xor_sync(0xffffffffu, mx1, 1));
        mx1 = fmaxf(mx1, __shfl_xor_sync(0xffffffffu, mx1, 2));
        float mn0 = fmaxf(m0, mx0 * CSCALE), mn1 = fmaxf(m1, mx1 * CSCALE);
        float cr0 = ex2(m0 - mn0), cr1 = ex2(m1 - mn1);
        float rs0 = 0.f, rs1 = 0.f;
        uint32_t Pp[8][2];
#pragma unroll
        for (int tn = 0; tn < 8; tn++) {
            float p0 = ex2(fmaf(S[tn][0], CSCALE, -mn0));
            float p1 = ex2(fmaf(S[tn][1], CSCALE, -mn0));
            float p2 = ex2(fmaf(S[tn][2], CSCALE, -mn1));
            float p3 = ex2(fmaf(S[tn][3], CSCALE, -mn1));
            rs0 += p0 + p1;
            rs1 += p2 + p3;
            Pp[tn][0] = packbf(p0, p1);
            Pp[tn][1] = packbf(p2, p3);
        }
        rs0 += __shfl_xor_sync(0xffffffffu, rs0, 1);
        rs0 += __shfl_xor_sync(0xffffffffu, rs0, 2);
        rs1 += __shfl_xor_sync(0xffffffffu, rs1, 1);
        rs1 += __shfl_xor_sync(0xffffffffu, rs1, 2);
        l0 = l0 * cr0 + rs0;  l1 = l1 * cr1 + rs1;
        m0 = mn0;  m1 = mn1;

#pragma unroll
        for (int tn = 0; tn < 8; tn++) {
            O[tn][0] *= cr0; O[tn][1] *= cr0;
            O[tn][2] *= cr1; O[tn][3] *= cr1;
        }

        // O += P @ V : 4 k16 steps over j (P in regs, V frags via LDS.64)
#pragma unroll
        for (int ks = 0; ks < 4; ks++) {
            uint32_t co = (uint32_t)(ks * 32);
            uint32_t a[4];
            a[0] = Pp[2 * ks][0];
            a[1] = Pp[2 * ks][1];
            a[2] = Pp[2 * ks + 1][0];
            a[3] = Pp[2 * ks + 1][1];
#pragma unroll
            for (int tn = 0; tn < 8; tn++) {
                uint32_t bfr[2];
                lds64(bfr[0], bfr[1], vBase + (uint32_t)(tn * 8 * 160) + co);
                mma16(O[tn], a, bfr);
            }
        }

        __syncthreads();
        if (kt + 2 < 16)
            attn_load_kv(sbase, b, K, V, kt + 2, tid);
        CP_COMMIT();
    }

    // epilogue -> g_att[n][s][head*64 + e] (bf16 pairs; unpermuted dims)
    int n = nh >> 3, head = nh & 7;
    float inv0 = 1.f / l0, inv1 = 1.f / l1;
    int srow0 = q0 + qb + g, srow1 = srow0 + 8;
    bf16* dst = g_att + (size_t)n * Ss * Cc + head * 64;
#pragma unroll
    for (int tn = 0; tn < 8; tn++) {
        int c = tn * 8 + 2 * tg;
        *(uint32_t*)&dst[(size_t)srow0 * Cc + c] = packbf(O[tn][0] * inv0, O[tn][1] * inv0);
        *(uint32_t*)&dst[(size_t)srow1 * Cc + c] = packbf(O[tn][2] * inv1, O[tn][3] * inv1);
    }
}

// ---------------------------------------------------------------------------
extern "C" void kernel_launch(void* const* d_in, const int* in_sizes, int n_in,
                              void* d_out, int out_size)
{
    const float* x    = (const float*)d_in[0];
    const float* gsc  = (const float*)d_in[1];
    const float* gbi  = (const float*)d_in[2];
    const float* wqkv = (const float*)d_in[3];
    const float* bqkv = (const float*)d_in[4];
    const float* wout = (const float*)d_in[5];
    const float* bout = (const float*)d_in[6];
    float* out = (float*)d_out;

    trans_kernel<<<dim3(16, 16, 4), dim3(32, 8)>>>(wqkv, wout);

    cudaFuncSetAttribute(gn_kernel, cudaFuncAttributeMaxDynamicSharedMemorySize, 69632);
    gn_kernel<<<Nn * 32, 256, 69632>>>(x, gsc, gbi);

    const int gemm_smem = 61440;
    cudaFuncSetAttribute(gemm_mma, cudaFuncAttributeMaxDynamicSharedMemorySize, gemm_smem);
    gemm_mma<<<dim3(Ss / 128, D3 / 128, Nn), 256, gemm_smem>>>(bqkv, nullptr, nullptr, 0);

    cudaFuncSetAttribute(attn_mma, cudaFuncAttributeMaxDynamicSharedMemorySize, ATT_SMEM);
    attn_mma<<<dim3(Ss / 128, Nn * NHEADS), 256, ATT_SMEM>>>();

    gemm_mma<<<dim3(Ss / 128, Cc / 128, Nn), 256, gemm_smem>>>(bout, x, out, 1);
}

// round 16
// speedup vs baseline: 1.1696x; 1.0456x over previous
#include <cuda_runtime.h>
#include <cuda_bf16.h>
#include <math.h>
#include <stdint.h>

// ---------------------------------------------------------------------------
// Problem constants
// ---------------------------------------------------------------------------
#define Nn 16            // B*T
#define Cc 512
#define Ss 1024          // H*W
#define NHEADS 8
#define HD 64
#define D3 1536          // 3*C

typedef __nv_bfloat16 bf16;

// ---------------------------------------------------------------------------
// Scratch.  ALL GEMM k-dims use the fragment-order permutation within each
// aligned 16-group: orig {2t,2t+1,2t+8,2t+9} -> positions {4t..4t+3}.
//   g_hn/g_att/g_wqkvT/g_woutT : c-dim permuted
//   g_q/g_k : e-dim permuted ;  g_v : s-dim permuted
// ---------------------------------------------------------------------------
__device__ bf16 g_hn   [Nn * Ss * Cc];           // [n][s][c-perm]
__device__ bf16 g_q    [Nn * NHEADS * Ss * HD];  // [nh][s][e-perm]
__device__ bf16 g_k    [Nn * NHEADS * Ss * HD];  // [nh][s][e-perm]
__device__ bf16 g_v    [Nn * NHEADS * HD * Ss];  // [nh][e][s-perm]
__device__ bf16 g_att  [Nn * Ss * Cc];           // [n][s][c-perm]
__device__ bf16 g_wqkvT[D3 * Cc];                // [d][c-perm]
__device__ bf16 g_woutT[Cc * Cc];                // [c2][c-perm]

// ---------------------------------------------------------------------------
// Helpers
// ---------------------------------------------------------------------------
__device__ __forceinline__ uint32_t smem_u32(const void* p) {
    uint32_t a;
    asm("{ .reg .u64 t; cvta.to.shared.u64 t, %1; cvt.u32.u64 %0, t; }"
        : "=r"(a) : "l"(p));
    return a;
}

__device__ __forceinline__ uint32_t packbf(float lo, float hi) {
    uint32_t r;
    asm("cvt.rn.bf16x2.f32 %0, %1, %2;" : "=r"(r) : "f"(hi), "f"(lo));
    return r;
}

__device__ __forceinline__ float ex2(float x) {
    float r;
    asm("ex2.approx.f32 %0, %1;" : "=f"(r) : "f"(x));
    return r;
}

__device__ __forceinline__ void mma16(float* d, const uint32_t* a, const uint32_t* b) {
    asm volatile(
        "mma.sync.aligned.m16n8k16.row.col.f32.bf16.bf16.f32 "
        "{%0,%1,%2,%3}, {%4,%5,%6,%7}, {%8,%9}, {%0,%1,%2,%3};"
        : "+f"(d[0]), "+f"(d[1]), "+f"(d[2]), "+f"(d[3])
        : "r"(a[0]), "r"(a[1]), "r"(a[2]), "r"(a[3]), "r"(b[0]), "r"(b[1]));
}

__device__ __forceinline__ void lds64(uint32_t& r0, uint32_t& r1, uint32_t addr) {
    asm volatile("ld.shared.v2.u32 {%0,%1}, [%2];" : "=r"(r0), "=r"(r1) : "r"(addr));
}

__device__ __forceinline__ void cp16(uint32_t dst, const void* src) {
    asm volatile("cp.async.cg.shared.global [%0], [%1], 16;" :: "r"(dst), "l"(src));
}
#define CP_COMMIT() asm volatile("cp.async.commit_group;" ::: "memory")
#define CP_WAIT1()  asm volatile("cp.async.wait_group 1;" ::: "memory")

// fragment-order permutation of index o within its aligned 16-group
__device__ __forceinline__ int fperm(int o) {
    int og = o & 15;
    return (o & ~15) + ((og >> 1) & 3) * 4 + (og >> 3) * 2 + (og & 1);
}

// ---------------------------------------------------------------------------
// Kernel 0: both weight transposes + bf16 rounding + c-perm, ONE launch.
// ---------------------------------------------------------------------------
__global__ void __launch_bounds__(256) trans_kernel(const float* __restrict__ wqkv,
                                                    const float* __restrict__ wout)
{
    int z = blockIdx.z;
    const float* in = (z < 3) ? wqkv : wout;
    bf16* out       = (z < 3) ? g_wqkvT : g_woutT;
    int Ccols       = (z < 3) ? D3 : Cc;
    int c0 = ((z < 3) ? (z * 16 + blockIdx.x) : blockIdx.x) * 32;
    int r0 = blockIdx.y * 32;

    __shared__ float t[32][33];
    int tx = threadIdx.x, ty = threadIdx.y;
#pragma unroll
    for (int i = 0; i < 32; i += 8)
        t[ty + i][tx] = in[(size_t)(r0 + ty + i) * Ccols + c0 + tx];
    __syncthreads();
    int txp = fperm(tx);       // r0 is 32-aligned so group structure holds
#pragma unroll
    for (int i = 0; i < 32; i += 8)
        out[(size_t)(c0 + ty + i) * 512 + r0 + txp] = __float2bfloat16_rn(t[tx][ty + i]);
}

// ---------------------------------------------------------------------------
// Kernel 1: GroupNorm -> g_hn [n][s][c-perm] (bf16).
// Block owns c-block g*16..g*16+15 == exactly one 16-group: permutation is a
// reorder of the 8 packed uint32 pairs.
// ---------------------------------------------------------------------------
__global__ void __launch_bounds__(256) gn_kernel(const float* __restrict__ x,
                                                 const float* __restrict__ sc,
                                                 const float* __restrict__ bi)
{
    extern __shared__ float smt[];   // [1024][17]
    int n = blockIdx.x >> 5;
    int g = blockIdx.x & 31;
    const float* px = x + (size_t)(n * Cc + g * 16) * Ss;
    bf16* ph = g_hn + (size_t)n * Ss * Cc + g * 16;
    int tid = threadIdx.x;
    const int M = 16 * Ss;

    float s = 0.f, ss = 0.f;
    for (int i = tid * 4; i < M; i += 1024) {
        int c  = i >> 10;
        int sp = i & 1023;
        float4 v = *(const float4*)&px[i];
        s  += v.x + v.y + v.z + v.w;
        ss += v.x*v.x + v.y*v.y + v.z*v.z + v.w*v.w;
        smt[(sp + 0) * 17 + c] = v.x;
        smt[(sp + 1) * 17 + c] = v.y;
        smt[(sp + 2) * 17 + c] = v.z;
        smt[(sp + 3) * 17 + c] = v.w;
    }
#pragma unroll
    for (int o = 16; o; o >>= 1) {
        s  += __shfl_xor_sync(0xffffffffu, s,  o);
        ss += __shfl_xor_sync(0xffffffffu, ss, o);
    }
    __shared__ float r0[8], r1[8];
    __shared__ float s_mean, s_inv;
    __shared__ float s_scv[16], s_biv[16];
    if ((tid & 31) == 0) { r0[tid >> 5] = s; r1[tid >> 5] = ss; }
    __syncthreads();
    if (tid == 0) {
        float a = 0.f, b2 = 0.f;
#pragma unroll
        for (int i = 0; i < 8; i++) { a += r0[i]; b2 += r1[i]; }
        float mean = a / (float)M;
        float var  = b2 / (float)M - mean * mean;
        s_mean = mean;
        s_inv  = rsqrtf(var + 1e-6f);
    }
    __syncthreads();
    if (tid < 16) {
        float scv = sc[g * 16 + tid] * s_inv;
        s_scv[tid] = scv;
        s_biv[tid] = bi[g * 16 + tid] - s_mean * scv;
    }
    __syncthreads();

#pragma unroll
    for (int j = 0; j < 4; j++) {
        int sp = tid * 4 + j;
        const float* row = &smt[sp * 17];
        uint32_t pk[8];
#pragma unroll
        for (int q = 0; q < 8; q++)
            pk[q] = packbf(row[2*q]   * s_scv[2*q]   + s_biv[2*q],
                           row[2*q+1] * s_scv[2*q+1] + s_biv[2*q+1]);
        uint4* dst = (uint4*)(ph + (size_t)sp * Cc);
        // permuted uint32 slot order: pk0,pk4,pk1,pk5,pk2,pk6,pk3,pk7
        dst[0] = make_uint4(pk[0], pk[4], pk[1], pk[5]);
        dst[1] = make_uint4(pk[2], pk[6], pk[3], pk[7]);
    }
}

// ---------------------------------------------------------------------------
// Kernel 2: bf16 m16n8k16 GEMM, tile 128x128, K=512, BK=32, 3-stage cp.async.
// 256 threads = 8 warps as 4(M) x 2(N); warp tile 32x64.
// Fragment-order c-perm -> every fragment is one LDS.64 (48 LDS.32 -> 24/kc).
// SMEM rows 48 bf16 (96 B, 24 words === 24 mod 32 -> conflict-free LDS.64).
// Stage = 128*96*2 = 24576 B; 3 stages = 73728 B.
// ---------------------------------------------------------------------------
__device__ __forceinline__ void gemm_load(uint32_t sbase, int soff,
                                          const bf16* __restrict__ Ag,
                                          const bf16* __restrict__ Bg,
                                          int koff, int tid)
{
#pragma unroll
    for (int i = 0; i < 2; i++) {
        int f = tid + i * 256;
        int row = f >> 2, c = f & 3;
        cp16(sbase + (uint32_t)(soff + row * 96 + c * 16),
             Ag + (size_t)row * Cc + koff + c * 8);
        cp16(sbase + (uint32_t)(soff + 12288 + row * 96 + c * 16),
             Bg + (size_t)row * Cc + koff + c * 8);
    }
}

__global__ void __launch_bounds__(256, 2) gemm_mma(const float* __restrict__ bias,
                                                   const float* __restrict__ xres,
                                                   float* __restrict__ out,
                                                   int mode)
{
    extern __shared__ char smc[];
    uint32_t sbase = smem_u32(smc);
    int tid = threadIdx.x, lane = tid & 31, wid = tid >> 5;
    int g = lane >> 2, tg = lane & 3;
    int n = blockIdx.z, s0 = blockIdx.x * 128, d0 = blockIdx.y * 128;
    int wm = wid & 3, wn = wid >> 2;

    const bf16* Ag = (mode ? g_att : g_hn) + ((size_t)n * Ss + s0) * Cc;
    const bf16* Bg = (mode ? g_woutT : g_wqkvT) + (size_t)d0 * Cc;

    float C[2][8][4] = {};

    gemm_load(sbase, 0, Ag, Bg, 0, tid);
    CP_COMMIT();
    gemm_load(sbase, 24576, Ag, Bg, 32, tid);
    CP_COMMIT();

    // per-lane fragment base addresses (byte): col offset = ks*32 + tg*8
    uint32_t aRow = (uint32_t)((wm * 32 + g) * 96 + tg * 8);
    uint32_t bRow = (uint32_t)(12288 + (wn * 64 + g) * 96 + tg * 8);

    for (int kc = 0; kc < 16; kc++) {
        CP_WAIT1();
        __syncthreads();
        int b = kc % 3;
        if (kc + 2 < 16)
            gemm_load(sbase, ((kc + 2) % 3) * 24576, Ag, Bg, (kc + 2) * 32, tid);
        CP_COMMIT();

        uint32_t stg = sbase + (uint32_t)(b * 24576);
#pragma unroll
        for (int ks = 0; ks < 2; ks++) {
            uint32_t co = (uint32_t)(ks * 32);
            uint32_t a[2][4], bb[8][2];
#pragma unroll
            for (int tm = 0; tm < 2; tm++) {
                uint32_t ra = stg + aRow + (uint32_t)(tm * 16 * 96) + co;
                lds64(a[tm][0], a[tm][2], ra);
                lds64(a[tm][1], a[tm][3], ra + 8 * 96);
            }
#pragma unroll
            for (int tn = 0; tn < 8; tn++)
                lds64(bb[tn][0], bb[tn][1], stg + bRow + (uint32_t)(tn * 8 * 96) + co);
#pragma unroll
            for (int tm = 0; tm < 2; tm++)
#pragma unroll
                for (int tn = 0; tn < 8; tn++)
                    mma16(C[tm][tn], a[tm], bb[tn]);
        }
    }

    // epilogue
#pragma unroll
    for (int tm = 0; tm < 2; tm++) {
#pragma unroll
        for (int hh = 0; hh < 2; hh++) {
            int m = s0 + wm * 32 + tm * 16 + g + hh * 8;
#pragma unroll
            for (int tn = 0; tn < 8; tn++) {
                int d = d0 + wn * 64 + tn * 8 + 2 * tg;
                float v0 = C[tm][tn][hh * 2 + 0] + __ldg(&bias[d]);
                float v1 = C[tm][tn][hh * 2 + 1] + __ldg(&bias[d + 1]);
                if (mode == 0) {
                    int head = d / 192, t = d % 192;
                    int part = t >> 6, e = t & 63;
                    size_t nh = (size_t)(n * 8 + head);
                    if (part < 2) {
                        int ep = fperm(e);     // e even -> pair lands adjacent
                        bf16* dst = part == 0 ? g_q : g_k;
                        *(uint32_t*)&dst[(nh * Ss + m) * HD + ep] = packbf(v0, v1);
                    } else {
                        int mp = fperm(m & 1023) + (m & ~1023);
                        g_v[(nh * HD + e) * Ss + mp]     = __float2bfloat16_rn(v0);
                        g_v[(nh * HD + e + 1) * Ss + mp] = __float2bfloat16_rn(v1);
                    }
                } else {
                    size_t gi = ((size_t)n * Cc + d) * Ss + m;
                    out[gi]      = v0 + xres[gi];
                    out[gi + Ss] = v1 + xres[gi + Ss];
                }
            }
        }
    }
}

// ---------------------------------------------------------------------------
// Kernel 3: flash attention, bf16 m16n8k16, double-buffered cp.async K/V,
// LDS.64 fragments (R15), exp2-domain softmax, c-permuted g_att epilogue.
// SMEM rows 80 bf16 (160 B); stage: K at b*20480, V +10240; Q at 40960.
// ---------------------------------------------------------------------------
#define ATT_SMEM 61440
#define CSCALE 0.18033688f   // 0.125 * log2(e)

__device__ __forceinline__ void attn_load_kv(uint32_t sbase, int b,
                                             const bf16* __restrict__ K,
                                             const bf16* __restrict__ V,
                                             int kt, int tid)
{
#pragma unroll
    for (int i = 0; i < 2; i++) {
        int f = tid + i * 256;
        int r = f >> 3, c = f & 7;
        cp16(sbase + (uint32_t)(b * 20480 + r * 160 + c * 16),
             K + (size_t)(kt * 64 + r) * HD + c * 8);
        cp16(sbase + (uint32_t)(b * 20480 + 10240 + r * 160 + c * 16),
             V + (size_t)r * Ss + kt * 64 + c * 8);
    }
}

__global__ void __launch_bounds__(256, 2) attn_mma()
{
    extern __shared__ char smc[];
    uint32_t sbase = smem_u32(smc);

    int tid = threadIdx.x, lane = tid & 31, w = tid >> 5;
    int g = lane >> 2, tg = lane & 3;
    int nh = blockIdx.y, q0 = blockIdx.x * 128;
    const bf16* Q = g_q + (size_t)nh * Ss * HD;
    const bf16* K = g_k + (size_t)nh * Ss * HD;
    const bf16* V = g_v + (size_t)nh * HD * Ss;

#pragma unroll
    for (int i = 0; i < 4; i++) {
        int f = tid + i * 256;
        int row = f >> 3, c = f & 7;
        cp16(sbase + (uint32_t)(40960 + row * 160 + c * 16),
             Q + (size_t)(q0 + row) * HD + c * 8);
    }
    attn_load_kv(sbase, 0, K, V, 0, tid);
    CP_COMMIT();
    attn_load_kv(sbase, 1, K, V, 1, tid);
    CP_COMMIT();

    float O[8][4] = {};
    float m0 = -1e30f, m1 = -1e30f, l0 = 0.f, l1 = 0.f;
    int qb = w * 16;

    uint32_t qRow0 = sbase + 40960u + (uint32_t)((qb + g) * 160) + (uint32_t)(tg * 8);
    uint32_t qRow1 = qRow0 + 8 * 160;

    for (int kt = 0; kt < 16; kt++) {
        CP_WAIT1();
        __syncthreads();
        int b = kt & 1;
        uint32_t kBase = sbase + (uint32_t)(b * 20480) + (uint32_t)(g * 160) + (uint32_t)(tg * 8);
        uint32_t vBase = kBase + 10240u;

        float S[8][4] = {};
#pragma unroll
        for (int ks = 0; ks < 4; ks++) {
            uint32_t co = (uint32_t)(ks * 32);
            uint32_t a[4];
            lds64(a[0], a[2], qRow0 + co);
            lds64(a[1], a[3], qRow1 + co);
#pragma unroll
            for (int tn = 0; tn < 8; tn++) {
                uint32_t bfr[2];
                lds64(bfr[0], bfr[1], kBase + (uint32_t)(tn * 8 * 160) + co);
                mma16(S[tn], a, bfr);
            }
        }

        float mx0 = -1e30f, mx1 = -1e30f;
#pragma unroll
        for (int tn = 0; tn < 8; tn++) {
            mx0 = fmaxf(mx0, fmaxf(S[tn][0], S[tn][1]));
            mx1 = fmaxf(mx1, fmaxf(S[tn][2], S[tn][3]));
        }
        mx0 = fmaxf(mx0, __shfl_xor_sync(0xffffffffu, mx0, 1));
        mx0 = fmaxf(mx0, __shfl_xor_sync(0xffffffffu, mx0, 2));
        mx1 = fmaxf(mx1, __shfl_xor_sync(0xffffffffu, mx1, 1));
        mx1 = fmaxf(mx1, __shfl_xor_sync(0xffffffffu, mx1, 2));
        float mn0 = fmaxf(m0, mx0 * CSCALE), mn1 = fmaxf(m1, mx1 * CSCALE);
        float cr0 = ex2(m0 - mn0), cr1 = ex2(m1 - mn1);
        float rs0 = 0.f, rs1 = 0.f;
        uint32_t Pp[8][2];
#pragma unroll
        for (int tn = 0; tn < 8; tn++) {
            float p0 = ex2(fmaf(S[tn][0], CSCALE, -mn0));
            float p1 = ex2(fmaf(S[tn][1], CSCALE, -mn0));
            float p2 = ex2(fmaf(S[tn][2], CSCALE, -mn1));
            float p3 = ex2(fmaf(S[tn][3], CSCALE, -mn1));
            rs0 += p0 + p1;
            rs1 += p2 + p3;
            Pp[tn][0] = packbf(p0, p1);
            Pp[tn][1] = packbf(p2, p3);
        }
        rs0 += __shfl_xor_sync(0xffffffffu, rs0, 1);
        rs0 += __shfl_xor_sync(0xffffffffu, rs0, 2);
        rs1 += __shfl_xor_sync(0xffffffffu, rs1, 1);
        rs1 += __shfl_xor_sync(0xffffffffu, rs1, 2);
        l0 = l0 * cr0 + rs0;  l1 = l1 * cr1 + rs1;
        m0 = mn0;  m1 = mn1;

#pragma unroll
        for (int tn = 0; tn < 8; tn++) {
            O[tn][0] *= cr0; O[tn][1] *= cr0;
            O[tn][2] *= cr1; O[tn][3] *= cr1;
        }

#pragma unroll
        for (int ks = 0; ks < 4; ks++) {
            uint32_t co = (uint32_t)(ks * 32);
            uint32_t a[4];
            a[0] = Pp[2 * ks][0];
            a[1] = Pp[2 * ks][1];
            a[2] = Pp[2 * ks + 1][0];
            a[3] = Pp[2 * ks + 1][1];
#pragma unroll
            for (int tn = 0; tn < 8; tn++) {
                uint32_t bfr[2];
                lds64(bfr[0], bfr[1], vBase + (uint32_t)(tn * 8 * 160) + co);
                mma16(O[tn], a, bfr);
            }
        }

        __syncthreads();
        if (kt + 2 < 16)
            attn_load_kv(sbase, b, K, V, kt + 2, tid);
        CP_COMMIT();
    }

    // epilogue -> g_att[n][s][c-perm] (bf16 pairs; c even so pair adjacent)
    int n = nh >> 3, head = nh & 7;
    float inv0 = 1.f / l0, inv1 = 1.f / l1;
    int srow0 = q0 + qb + g, srow1 = srow0 + 8;
    bf16* dst = g_att + (size_t)n * Ss * Cc + head * 64;
#pragma unroll
    for (int tn = 0; tn < 8; tn++) {
        int c = tn * 8 + 2 * tg;
        int cp = fperm(c);
        *(uint32_t*)&dst[(size_t)srow0 * Cc + cp] = packbf(O[tn][0] * inv0, O[tn][1] * inv0);
        *(uint32_t*)&dst[(size_t)srow1 * Cc + cp] = packbf(O[tn][2] * inv1, O[tn][3] * inv1);
    }
}

// ---------------------------------------------------------------------------
extern "C" void kernel_launch(void* const* d_in, const int* in_sizes, int n_in,
                              void* d_out, int out_size)
{
    const float* x    = (const float*)d_in[0];
    const float* gsc  = (const float*)d_in[1];
    const float* gbi  = (const float*)d_in[2];
    const float* wqkv = (const float*)d_in[3];
    const float* bqkv = (const float*)d_in[4];
    const float* wout = (const float*)d_in[5];
    const float* bout = (const float*)d_in[6];
    float* out = (float*)d_out;

    trans_kernel<<<dim3(16, 16, 4), dim3(32, 8)>>>(wqkv, wout);

    cudaFuncSetAttribute(gn_kernel, cudaFuncAttributeMaxDynamicSharedMemorySize, 69632);
    gn_kernel<<<Nn * 32, 256, 69632>>>(x, gsc, gbi);

    const int gemm_smem = 73728;   // 3 stages x 24576 B
    cudaFuncSetAttribute(gemm_mma, cudaFuncAttributeMaxDynamicSharedMemorySize, gemm_smem);
    gemm_mma<<<dim3(Ss / 128, D3 / 128, Nn), 256, gemm_smem>>>(bqkv, nullptr, nullptr, 0);

    cudaFuncSetAttribute(attn_mma, cudaFuncAttributeMaxDynamicSharedMemorySize, ATT_SMEM);
    attn_mma<<<dim3(Ss / 128, Nn * NHEADS), 256, ATT_SMEM>>>();

    gemm_mma<<<dim3(Ss / 128, Cc / 128, Nn), 256, gemm_smem>>>(bout, x, out, 1);
}

// round 17
// speedup vs baseline: 1.1848x; 1.0130x over previous
#include <cuda_runtime.h>
#include <cuda_bf16.h>
#include <math.h>
#include <stdint.h>

// ---------------------------------------------------------------------------
// Problem constants
// ---------------------------------------------------------------------------
#define Nn 16            // B*T
#define Cc 512
#define Ss 1024          // H*W
#define NHEADS 8
#define HD 64
#define D3 1536          // 3*C

typedef __nv_bfloat16 bf16;

// ---------------------------------------------------------------------------
// Scratch.  ALL GEMM k-dims use the fragment-order permutation within each
// aligned 16-group: orig {2t,2t+1,2t+8,2t+9} -> positions {4t..4t+3}.
// ---------------------------------------------------------------------------
__device__ bf16 g_hn   [Nn * Ss * Cc];           // [n][s][c-perm]
__device__ bf16 g_q    [Nn * NHEADS * Ss * HD];  // [nh][s][e-perm]
__device__ bf16 g_k    [Nn * NHEADS * Ss * HD];  // [nh][s][e-perm]
__device__ bf16 g_v    [Nn * NHEADS * HD * Ss];  // [nh][e][s-perm]
__device__ bf16 g_att  [Nn * Ss * Cc];           // [n][s][c-perm]
__device__ bf16 g_wqkvT[D3 * Cc];                // [d][c-perm]
__device__ bf16 g_woutT[Cc * Cc];                // [c2][c-perm]

// ---------------------------------------------------------------------------
// Helpers
// ---------------------------------------------------------------------------
__device__ __forceinline__ uint32_t smem_u32(const void* p) {
    uint32_t a;
    asm("{ .reg .u64 t; cvta.to.shared.u64 t, %1; cvt.u32.u64 %0, t; }"
        : "=r"(a) : "l"(p));
    return a;
}

__device__ __forceinline__ uint32_t packbf(float lo, float hi) {
    uint32_t r;
    asm("cvt.rn.bf16x2.f32 %0, %1, %2;" : "=r"(r) : "f"(hi), "f"(lo));
    return r;
}

__device__ __forceinline__ float ex2(float x) {
    float r;
    asm("ex2.approx.f32 %0, %1;" : "=f"(r) : "f"(x));
    return r;
}

__device__ __forceinline__ void mma16(float* d, const uint32_t* a, const uint32_t* b) {
    asm volatile(
        "mma.sync.aligned.m16n8k16.row.col.f32.bf16.bf16.f32 "
        "{%0,%1,%2,%3}, {%4,%5,%6,%7}, {%8,%9}, {%0,%1,%2,%3};"
        : "+f"(d[0]), "+f"(d[1]), "+f"(d[2]), "+f"(d[3])
        : "r"(a[0]), "r"(a[1]), "r"(a[2]), "r"(a[3]), "r"(b[0]), "r"(b[1]));
}

__device__ __forceinline__ void lds64(uint32_t& r0, uint32_t& r1, uint32_t addr) {
    asm volatile("ld.shared.v2.u32 {%0,%1}, [%2];" : "=r"(r0), "=r"(r1) : "r"(addr));
}

__device__ __forceinline__ void cp16(uint32_t dst, const void* src) {
    asm volatile("cp.async.cg.shared.global [%0], [%1], 16;" :: "r"(dst), "l"(src));
}
#define CP_COMMIT() asm volatile("cp.async.commit_group;" ::: "memory")
#define CP_WAIT1()  asm volatile("cp.async.wait_group 1;" ::: "memory")

// fragment-order permutation of index o within its aligned 16-group
__device__ __forceinline__ int fperm(int o) {
    int og = o & 15;
    return (o & ~15) + ((og >> 1) & 3) * 4 + (og >> 3) * 2 + (og & 1);
}

// ---------------------------------------------------------------------------
// Kernel 0: both weight transposes + bf16 rounding + c-perm, ONE launch.
// ---------------------------------------------------------------------------
__global__ void __launch_bounds__(256) trans_kernel(const float* __restrict__ wqkv,
                                                    const float* __restrict__ wout)
{
    int z = blockIdx.z;
    const float* in = (z < 3) ? wqkv : wout;
    bf16* out       = (z < 3) ? g_wqkvT : g_woutT;
    int Ccols       = (z < 3) ? D3 : Cc;
    int c0 = ((z < 3) ? (z * 16 + blockIdx.x) : blockIdx.x) * 32;
    int r0 = blockIdx.y * 32;

    __shared__ float t[32][33];
    int tx = threadIdx.x, ty = threadIdx.y;
#pragma unroll
    for (int i = 0; i < 32; i += 8)
        t[ty + i][tx] = in[(size_t)(r0 + ty + i) * Ccols + c0 + tx];
    __syncthreads();
    int txp = fperm(tx);
#pragma unroll
    for (int i = 0; i < 32; i += 8)
        out[(size_t)(c0 + ty + i) * 512 + r0 + txp] = __float2bfloat16_rn(t[tx][ty + i]);
}

// ---------------------------------------------------------------------------
// Kernel 1: GroupNorm -> g_hn [n][s][c-perm] (bf16), single global read.
// ---------------------------------------------------------------------------
__global__ void __launch_bounds__(256) gn_kernel(const float* __restrict__ x,
                                                 const float* __restrict__ sc,
                                                 const float* __restrict__ bi)
{
    extern __shared__ float smt[];   // [1024][17]
    int n = blockIdx.x >> 5;
    int g = blockIdx.x & 31;
    const float* px = x + (size_t)(n * Cc + g * 16) * Ss;
    bf16* ph = g_hn + (size_t)n * Ss * Cc + g * 16;
    int tid = threadIdx.x;
    const int M = 16 * Ss;

    float s = 0.f, ss = 0.f;
    for (int i = tid * 4; i < M; i += 1024) {
        int c  = i >> 10;
        int sp = i & 1023;
        float4 v = *(const float4*)&px[i];
        s  += v.x + v.y + v.z + v.w;
        ss += v.x*v.x + v.y*v.y + v.z*v.z + v.w*v.w;
        smt[(sp + 0) * 17 + c] = v.x;
        smt[(sp + 1) * 17 + c] = v.y;
        smt[(sp + 2) * 17 + c] = v.z;
        smt[(sp + 3) * 17 + c] = v.w;
    }
#pragma unroll
    for (int o = 16; o; o >>= 1) {
        s  += __shfl_xor_sync(0xffffffffu, s,  o);
        ss += __shfl_xor_sync(0xffffffffu, ss, o);
    }
    __shared__ float r0[8], r1[8];
    __shared__ float s_mean, s_inv;
    __shared__ float s_scv[16], s_biv[16];
    if ((tid & 31) == 0) { r0[tid >> 5] = s; r1[tid >> 5] = ss; }
    __syncthreads();
    if (tid == 0) {
        float a = 0.f, b2 = 0.f;
#pragma unroll
        for (int i = 0; i < 8; i++) { a += r0[i]; b2 += r1[i]; }
        float mean = a / (float)M;
        float var  = b2 / (float)M - mean * mean;
        s_mean = mean;
        s_inv  = rsqrtf(var + 1e-6f);
    }
    __syncthreads();
    if (tid < 16) {
        float scv = sc[g * 16 + tid] * s_inv;
        s_scv[tid] = scv;
        s_biv[tid] = bi[g * 16 + tid] - s_mean * scv;
    }
    __syncthreads();

#pragma unroll
    for (int j = 0; j < 4; j++) {
        int sp = tid * 4 + j;
        const float* row = &smt[sp * 17];
        uint32_t pk[8];
#pragma unroll
        for (int q = 0; q < 8; q++)
            pk[q] = packbf(row[2*q]   * s_scv[2*q]   + s_biv[2*q],
                           row[2*q+1] * s_scv[2*q+1] + s_biv[2*q+1]);
        uint4* dst = (uint4*)(ph + (size_t)sp * Cc);
        dst[0] = make_uint4(pk[0], pk[4], pk[1], pk[5]);
        dst[1] = make_uint4(pk[2], pk[6], pk[3], pk[7]);
    }
}

// ---------------------------------------------------------------------------
// Kernel 2: bf16 m16n8k16 GEMM, tile 128x128, K=512, BK=32, 3-stage cp.async,
// LDS.64 fragments via c-perm.  (R16 verbatim.)
// ---------------------------------------------------------------------------
__device__ __forceinline__ void gemm_load(uint32_t sbase, int soff,
                                          const bf16* __restrict__ Ag,
                                          const bf16* __restrict__ Bg,
                                          int koff, int tid)
{
#pragma unroll
    for (int i = 0; i < 2; i++) {
        int f = tid + i * 256;
        int row = f >> 2, c = f & 3;
        cp16(sbase + (uint32_t)(soff + row * 96 + c * 16),
             Ag + (size_t)row * Cc + koff + c * 8);
        cp16(sbase + (uint32_t)(soff + 12288 + row * 96 + c * 16),
             Bg + (size_t)row * Cc + koff + c * 8);
    }
}

__global__ void __launch_bounds__(256, 2) gemm_mma(const float* __restrict__ bias,
                                                   const float* __restrict__ xres,
                                                   float* __restrict__ out,
                                                   int mode)
{
    extern __shared__ char smc[];
    uint32_t sbase = smem_u32(smc);
    int tid = threadIdx.x, lane = tid & 31, wid = tid >> 5;
    int g = lane >> 2, tg = lane & 3;
    int n = blockIdx.z, s0 = blockIdx.x * 128, d0 = blockIdx.y * 128;
    int wm = wid & 3, wn = wid >> 2;

    const bf16* Ag = (mode ? g_att : g_hn) + ((size_t)n * Ss + s0) * Cc;
    const bf16* Bg = (mode ? g_woutT : g_wqkvT) + (size_t)d0 * Cc;

    float C[2][8][4] = {};

    gemm_load(sbase, 0, Ag, Bg, 0, tid);
    CP_COMMIT();
    gemm_load(sbase, 24576, Ag, Bg, 32, tid);
    CP_COMMIT();

    uint32_t aRow = (uint32_t)((wm * 32 + g) * 96 + tg * 8);
    uint32_t bRow = (uint32_t)(12288 + (wn * 64 + g) * 96 + tg * 8);

    for (int kc = 0; kc < 16; kc++) {
        CP_WAIT1();
        __syncthreads();
        int b = kc % 3;
        if (kc + 2 < 16)
            gemm_load(sbase, ((kc + 2) % 3) * 24576, Ag, Bg, (kc + 2) * 32, tid);
        CP_COMMIT();

        uint32_t stg = sbase + (uint32_t)(b * 24576);
#pragma unroll
        for (int ks = 0; ks < 2; ks++) {
            uint32_t co = (uint32_t)(ks * 32);
            uint32_t a[2][4], bb[8][2];
#pragma unroll
            for (int tm = 0; tm < 2; tm++) {
                uint32_t ra = stg + aRow + (uint32_t)(tm * 16 * 96) + co;
                lds64(a[tm][0], a[tm][2], ra);
                lds64(a[tm][1], a[tm][3], ra + 8 * 96);
            }
#pragma unroll
            for (int tn = 0; tn < 8; tn++)
                lds64(bb[tn][0], bb[tn][1], stg + bRow + (uint32_t)(tn * 8 * 96) + co);
#pragma unroll
            for (int tm = 0; tm < 2; tm++)
#pragma unroll
                for (int tn = 0; tn < 8; tn++)
                    mma16(C[tm][tn], a[tm], bb[tn]);
        }
    }

    // epilogue
#pragma unroll
    for (int tm = 0; tm < 2; tm++) {
#pragma unroll
        for (int hh = 0; hh < 2; hh++) {
            int m = s0 + wm * 32 + tm * 16 + g + hh * 8;
#pragma unroll
            for (int tn = 0; tn < 8; tn++) {
                int d = d0 + wn * 64 + tn * 8 + 2 * tg;
                float v0 = C[tm][tn][hh * 2 + 0] + __ldg(&bias[d]);
                float v1 = C[tm][tn][hh * 2 + 1] + __ldg(&bias[d + 1]);
                if (mode == 0) {
                    int head = d / 192, t = d % 192;
                    int part = t >> 6, e = t & 63;
                    size_t nh = (size_t)(n * 8 + head);
                    if (part < 2) {
                        int ep = fperm(e);
                        bf16* dst = part == 0 ? g_q : g_k;
                        *(uint32_t*)&dst[(nh * Ss + m) * HD + ep] = packbf(v0, v1);
                    } else {
                        int mp = fperm(m & 1023) + (m & ~1023);
                        g_v[(nh * HD + e) * Ss + mp]     = __float2bfloat16_rn(v0);
                        g_v[(nh * HD + e + 1) * Ss + mp] = __float2bfloat16_rn(v1);
                    }
                } else {
                    size_t gi = ((size_t)n * Cc + d) * Ss + m;
                    out[gi]      = v0 + xres[gi];
                    out[gi + Ss] = v1 + xres[gi + Ss];
                }
            }
        }
    }
}

// ---------------------------------------------------------------------------
// Kernel 3: flash attention, bf16 m16n8k16.
// 3-stage cp.async KV ring (ONE __syncthreads per tile, prefetch issued
// before compute), Q fragments hoisted to registers (loaded once),
// LDS.64 fragments, exp2-domain softmax.
// SMEM: stage st (0..2): K at st*20480, V at +10240; Q at 61440. 81920 B.
// ---------------------------------------------------------------------------
#define ATT_SMEM 81920
#define CSCALE 0.18033688f   // 0.125 * log2(e)

__device__ __forceinline__ void attn_load_kv(uint32_t sbase, int st,
                                             const bf16* __restrict__ K,
                                             const bf16* __restrict__ V,
                                             int kt, int tid)
{
#pragma unroll
    for (int i = 0; i < 2; i++) {
        int f = tid + i * 256;
        int r = f >> 3, c = f & 7;
        cp16(sbase + (uint32_t)(st * 20480 + r * 160 + c * 16),
             K + (size_t)(kt * 64 + r) * HD + c * 8);
        cp16(sbase + (uint32_t)(st * 20480 + 10240 + r * 160 + c * 16),
             V + (size_t)r * Ss + kt * 64 + c * 8);
    }
}

__global__ void __launch_bounds__(256, 2) attn_mma()
{
    extern __shared__ char smc[];
    uint32_t sbase = smem_u32(smc);

    int tid = threadIdx.x, lane = tid & 31, w = tid >> 5;
    int g = lane >> 2, tg = lane & 3;
    int nh = blockIdx.y, q0 = blockIdx.x * 128;
    const bf16* Q = g_q + (size_t)nh * Ss * HD;
    const bf16* K = g_k + (size_t)nh * Ss * HD;
    const bf16* V = g_v + (size_t)nh * HD * Ss;

    // prologue: G0 = {Q, KV0}; G1 = {KV1}
#pragma unroll
    for (int i = 0; i < 4; i++) {
        int f = tid + i * 256;
        int row = f >> 3, c = f & 7;
        cp16(sbase + (uint32_t)(61440 + row * 160 + c * 16),
             Q + (size_t)(q0 + row) * HD + c * 8);
    }
    attn_load_kv(sbase, 0, K, V, 0, tid);
    CP_COMMIT();
    attn_load_kv(sbase, 1, K, V, 1, tid);
    CP_COMMIT();

    int qb = w * 16;

    // wait G0 (Q + KV0 ready), hoist Q fragments to registers
    CP_WAIT1();
    __syncthreads();
    uint32_t qa[4][4];
    {
        uint32_t qRow0 = sbase + 61440u + (uint32_t)((qb + g) * 160) + (uint32_t)(tg * 8);
        uint32_t qRow1 = qRow0 + 8 * 160;
#pragma unroll
        for (int ks = 0; ks < 4; ks++) {
            lds64(qa[ks][0], qa[ks][2], qRow0 + (uint32_t)(ks * 32));
            lds64(qa[ks][1], qa[ks][3], qRow1 + (uint32_t)(ks * 32));
        }
    }
    // prefetch KV2 into stage 2 -> G2
    attn_load_kv(sbase, 2, K, V, 2, tid);
    CP_COMMIT();

    float O[8][4] = {};
    float m0 = -1e30f, m1 = -1e30f, l0 = 0.f, l1 = 0.f;

    for (int kt = 0; kt < 16; kt++) {
        if (kt > 0) {
            CP_WAIT1();          // G_kt complete (G_{kt+1} may be in flight)
            __syncthreads();     // all warps done with stage (kt-1)%3
            if (kt + 2 < 16)
                attn_load_kv(sbase, (kt + 2) % 3, K, V, kt + 2, tid);
            CP_COMMIT();
        }
        int st = kt % 3;
        uint32_t kBase = sbase + (uint32_t)(st * 20480) + (uint32_t)(g * 160) + (uint32_t)(tg * 8);
        uint32_t vBase = kBase + 10240u;

        // S = Q @ K^T (Q frags from registers)
        float S[8][4] = {};
#pragma unroll
        for (int ks = 0; ks < 4; ks++) {
            uint32_t co = (uint32_t)(ks * 32);
#pragma unroll
            for (int tn = 0; tn < 8; tn++) {
                uint32_t bfr[2];
                lds64(bfr[0], bfr[1], kBase + (uint32_t)(tn * 8 * 160) + co);
                mma16(S[tn], qa[ks], bfr);
            }
        }

        // online softmax in exp2 domain
        float mx0 = -1e30f, mx1 = -1e30f;
#pragma unroll
        for (int tn = 0; tn < 8; tn++) {
            mx0 = fmaxf(mx0, fmaxf(S[tn][0], S[tn][1]));
            mx1 = fmaxf(mx1, fmaxf(S[tn][2], S[tn][3]));
        }
        mx0 = fmaxf(mx0, __shfl_xor_sync(0xffffffffu, mx0, 1));
        mx0 = fmaxf(mx0, __shfl_xor_sync(0xffffffffu, mx0, 2));
        mx1 = fmaxf(mx1, __shfl_xor_sync(0xffffffffu, mx1, 1));
        mx1 = fmaxf(mx1, __shfl_xor_sync(0xffffffffu, mx1, 2));
        float mn0 = fmaxf(m0, mx0 * CSCALE), mn1 = fmaxf(m1, mx1 * CSCALE);
        float cr0 = ex2(m0 - mn0), cr1 = ex2(m1 - mn1);
        float rs0 = 0.f, rs1 = 0.f;
        uint32_t Pp[8][2];
#pragma unroll
        for (int tn = 0; tn < 8; tn++) {
            float p0 = ex2(fmaf(S[tn][0], CSCALE, -mn0));
            float p1 = ex2(fmaf(S[tn][1], CSCALE, -mn0));
            float p2 = ex2(fmaf(S[tn][2], CSCALE, -mn1));
            float p3 = ex2(fmaf(S[tn][3], CSCALE, -mn1));
            rs0 += p0 + p1;
            rs1 += p2 + p3;
            Pp[tn][0] = packbf(p0, p1);
            Pp[tn][1] = packbf(p2, p3);
        }
        rs0 += __shfl_xor_sync(0xffffffffu, rs0, 1);
        rs0 += __shfl_xor_sync(0xffffffffu, rs0, 2);
        rs1 += __shfl_xor_sync(0xffffffffu, rs1, 1);
        rs1 += __shfl_xor_sync(0xffffffffu, rs1, 2);
        l0 = l0 * cr0 + rs0;  l1 = l1 * cr1 + rs1;
        m0 = mn0;  m1 = mn1;

#pragma unroll
        for (int tn = 0; tn < 8; tn++) {
            O[tn][0] *= cr0; O[tn][1] *= cr0;
            O[tn][2] *= cr1; O[tn][3] *= cr1;
        }

        // O += P @ V
#pragma unroll
        for (int ks = 0; ks < 4; ks++) {
            uint32_t co = (uint32_t)(ks * 32);
            uint32_t a[4];
            a[0] = Pp[2 * ks][0];
            a[1] = Pp[2 * ks][1];
            a[2] = Pp[2 * ks + 1][0];
            a[3] = Pp[2 * ks + 1][1];
#pragma unroll
            for (int tn = 0; tn < 8; tn++) {
                uint32_t bfr[2];
                lds64(bfr[0], bfr[1], vBase + (uint32_t)(tn * 8 * 160) + co);
                mma16(O[tn], a, bfr);
            }
        }
    }

    // epilogue -> g_att[n][s][c-perm]
    int n = nh >> 3, head = nh & 7;
    float inv0 = 1.f / l0, inv1 = 1.f / l1;
    int srow0 = q0 + qb + g, srow1 = srow0 + 8;
    bf16* dst = g_att + (size_t)n * Ss * Cc + head * 64;
#pragma unroll
    for (int tn = 0; tn < 8; tn++) {
        int c = tn * 8 + 2 * tg;
        int cp = fperm(c);
        *(uint32_t*)&dst[(size_t)srow0 * Cc + cp] = packbf(O[tn][0] * inv0, O[tn][1] * inv0);
        *(uint32_t*)&dst[(size_t)srow1 * Cc + cp] = packbf(O[tn][2] * inv1, O[tn][3] * inv1);
    }
}

// ---------------------------------------------------------------------------
extern "C" void kernel_launch(void* const* d_in, const int* in_sizes, int n_in,
                              void* d_out, int out_size)
{
    const float* x    = (const float*)d_in[0];
    const float* gsc  = (const float*)d_in[1];
    const float* gbi  = (const float*)d_in[2];
    const float* wqkv = (const float*)d_in[3];
    const float* bqkv = (const float*)d_in[4];
    const float* wout = (const float*)d_in[5];
    const float* bout = (const float*)d_in[6];
    float* out = (float*)d_out;

    trans_kernel<<<dim3(16, 16, 4), dim3(32, 8)>>>(wqkv, wout);

    cudaFuncSetAttribute(gn_kernel, cudaFuncAttributeMaxDynamicSharedMemorySize, 69632);
    gn_kernel<<<Nn * 32, 256, 69632>>>(x, gsc, gbi);

    const int gemm_smem = 73728;   // 3 stages x 24576 B
    cudaFuncSetAttribute(gemm_mma, cudaFuncAttributeMaxDynamicSharedMemorySize, gemm_smem);
    gemm_mma<<<dim3(Ss / 128, D3 / 128, Nn), 256, gemm_smem>>>(bqkv, nullptr, nullptr, 0);

    cudaFuncSetAttribute(attn_mma, cudaFuncAttributeMaxDynamicSharedMemorySize, ATT_SMEM);
    attn_mma<<<dim3(Ss / 128, Nn * NHEADS), 256, ATT_SMEM>>>();

    gemm_mma<<<dim3(Ss / 128, Cc / 128, Nn), 256, gemm_smem>>>(bout, x, out, 1);
}